// round 7
// baseline (speedup 1.0000x reference)
#include <cuda_runtime.h>
#include <cuda_bf16.h>
#include <math.h>

// ---------------- problem constants ----------------
#define BATCH 256
#define SIG_LEN 2048
#define NCH 3
#define O1 128
#define P1 1022          // conv1(k3) -> 2046, pool k3 s2 -> 1022
#define O2 64
#define P2 339           // conv2(k5) -> 1018, pool k3 s3 -> 339
#define O3 64
#define P3 168           // conv3(k3) -> 337, pool k3 s2 -> 168
#define FC_IN 10752      // 64*168
#define EPS_BN 1e-5f
#define FC_NS 28
#define FC_KC 384        // FC_IN / FC_NS

// conv2-TC smem layout (floats)
#define WS_STR 72        // 72 % 32 == 8 -> conflict-free A-frag loads
#define HS_STR 104       // 104 % 32 == 8 -> conflict-free B-frag loads
#define SD_STR 97
#define OFF_WSHI 0
#define OFF_WSLO (80 * WS_STR)
#define OFF_HSHI (2 * 80 * WS_STR)
#define OFF_HSLO (2 * 80 * WS_STR + 16 * HS_STR)
#define OFF_SD   (2 * 80 * WS_STR + 2 * 16 * HS_STR)
#define SMEM_FLOATS (OFF_SD + 64 * SD_STR)

// ---------------- device scratch (no allocations allowed) ----------------
__device__ float g_h1[(size_t)BATCH * O1 * P1];   // 134 MB
__device__ float g_h2[(size_t)BATCH * O2 * P2];   // 22 MB
__device__ float g_h3[(size_t)BATCH * O3 * P3];   // 11 MB
__device__ float g_fc1p[FC_NS][BATCH][48];
__device__ float g_A[BATCH * 12];

// ---------------- tf32 helpers ----------------
__device__ __forceinline__ unsigned f2tf32(float x) {
    unsigned r; asm("cvt.rna.tf32.f32 %0, %1;" : "=r"(r) : "f"(x)); return r;
}
__device__ __forceinline__ void split_tf32(float x, float& hi, float& lo) {
    unsigned h = f2tf32(x);
    hi = __uint_as_float(h);
    lo = __uint_as_float(f2tf32(x - hi));
}
__device__ __forceinline__ void mma8(float* d, const unsigned* a, unsigned b0, unsigned b1) {
    asm volatile(
        "mma.sync.aligned.m16n8k8.row.col.f32.tf32.tf32.f32 "
        "{%0,%1,%2,%3}, {%4,%5,%6,%7}, {%8,%9}, {%0,%1,%2,%3};"
        : "+f"(d[0]), "+f"(d[1]), "+f"(d[2]), "+f"(d[3])
        : "r"(a[0]), "r"(a[1]), "r"(a[2]), "r"(a[3]), "r"(b0), "r"(b1));
}

// ============================================================
// Kernel 1: conv1(k3) + BN + maxpool(3,2) + ReLU  -> g_h1
// ============================================================
__global__ void k_conv1(const float* __restrict__ x, const float* __restrict__ w,
                        const float* __restrict__ cb, const float* __restrict__ g,
                        const float* __restrict__ be, const float* __restrict__ m,
                        const float* __restrict__ v) {
    __shared__ float ws[O1 * 9];
    __shared__ float Ss[O1], Ts[O1];
    int b = blockIdx.y;
    int tid = threadIdx.x;
    for (int i = tid; i < O1 * 9; i += 128) ws[i] = w[i];
    if (tid < O1) {
        float s = g[tid] * rsqrtf(v[tid] + EPS_BN);
        Ss[tid] = s;
        Ts[tid] = (cb[tid] - m[tid]) * s + be[tid];
    }
    __syncthreads();
    int j = blockIdx.x * 128 + tid;
    if (j >= P1) return;

    const float* xb = x + (size_t)b * NCH * SIG_LEN;
    float xv[3][5];
#pragma unroll
    for (int c = 0; c < 3; c++)
#pragma unroll
        for (int k = 0; k < 5; k++)
            xv[c][k] = xb[c * SIG_LEN + 2 * j + k];

    float* h1 = g_h1 + (size_t)b * O1 * P1;
#pragma unroll 4
    for (int o = 0; o < O1; o++) {
        const float* wo = ws + o * 9;
        float y0 = 0.f, y1 = 0.f, y2 = 0.f;
#pragma unroll
        for (int c = 0; c < 3; c++) {
#pragma unroll
            for (int k = 0; k < 3; k++) {
                float wv = wo[c * 3 + k];
                y0 += xv[c][k] * wv;
                y1 += xv[c][k + 1] * wv;
                y2 += xv[c][k + 2] * wv;
            }
        }
        float S = Ss[o], T = Ts[o];
        float r = fmaxf(fmaxf(y0 * S + T, y1 * S + T), y2 * S + T);
        h1[(size_t)o * P1 + j] = fmaxf(r, 0.f);
    }
}

// ============================================================
// Kernel 2: conv2 via 3xTF32 tensor-core implicit GEMM.
// Block = (b, 32 pooled j) = 96 pre-pool positions (pool s3: non-overlap).
// M=64 (o), N=96, K=640 (c*5+k, ordered kk = k*16+cc per 16-c chunk).
// 8 warps: warp = (otile 0..3) x (nhalf 0..1); warp tile M16 x N48.
// 3 MMA passes per frag: Ahi*Bhi + Ahi*Blo + Alo*Bhi (split-fp32 precision).
// Epilogue: D -> smem -> maxpool(3,3) + BN + ReLU -> g_h2.
// ============================================================
__global__ void k_conv2tc(const float* __restrict__ w, const float* __restrict__ cb,
                          const float* __restrict__ g, const float* __restrict__ be,
                          const float* __restrict__ m, const float* __restrict__ v) {
    extern __shared__ float sm[];
    float* ws_hi = sm + OFF_WSHI;   // [80][WS_STR]
    float* ws_lo = sm + OFF_WSLO;
    float* hs_hi = sm + OFF_HSHI;   // [16][HS_STR]
    float* hs_lo = sm + OFF_HSLO;
    float* sdout = sm + OFF_SD;     // [64][SD_STR]
    __shared__ float Ss[O2], Ts[O2];

    int b = blockIdx.y;
    int j0 = blockIdx.x * 32;
    int tid = threadIdx.x;
    if (tid < O2) {
        float s = g[tid] * rsqrtf(v[tid] + EPS_BN);
        Ss[tid] = s;
        Ts[tid] = (cb[tid] - m[tid]) * s + be[tid];
    }
    int lane = tid & 31, wid = tid >> 5;
    int gid = lane >> 2, tig = lane & 3;
    int obase = (wid & 3) * 16;
    int nb0 = (wid >> 2) * 48;

    float acc[6][4];
#pragma unroll
    for (int i = 0; i < 6; i++)
#pragma unroll
        for (int jq = 0; jq < 4; jq++) acc[i][jq] = 0.f;

    const float* h1b = g_h1 + (size_t)b * O1 * P1;
    int gbase = 3 * j0;

    for (int c0 = 0; c0 < O1; c0 += 16) {
        __syncthreads();
        // stage h1 tile, split hi/lo tf32 at fill time
        for (int idx = tid; idx < 16 * 100; idx += 256) {
            int cc = idx / 100, p = idx - cc * 100;
            int gp = gbase + p;
            float xv = (gp < P1) ? h1b[(size_t)(c0 + cc) * P1 + gp] : 0.f;
            float hf, lf; split_tf32(xv, hf, lf);
            hs_hi[cc * HS_STR + p] = hf;
            hs_lo[cc * HS_STR + p] = lf;
        }
        // stage weights transposed [kk = k*16+cc][o], split hi/lo
        for (int idx = tid; idx < 80 * 64; idx += 256) {
            int kk = idx >> 6, o = idx & 63;
            int k = kk >> 4, cc = kk & 15;
            float xv = w[o * 640 + (c0 + cc) * 5 + k];
            float hf, lf; split_tf32(xv, hf, lf);
            ws_hi[kk * WS_STR + o] = hf;
            ws_lo[kk * WS_STR + o] = lf;
        }
        __syncthreads();
#pragma unroll
        for (int s = 0; s < 10; s++) {
            int kkb = s * 8;
            int kq = s >> 1;            // conv tap for all 8 K-rows of this step
            int ccb = (s & 1) * 8;      // channel base within chunk
            unsigned a_hi[4], a_lo[4];
            {
                int r0 = (kkb + tig) * WS_STR + obase + gid;
                int r1 = (kkb + tig + 4) * WS_STR + obase + gid;
                a_hi[0] = __float_as_uint(ws_hi[r0]);
                a_hi[1] = __float_as_uint(ws_hi[r0 + 8]);
                a_hi[2] = __float_as_uint(ws_hi[r1]);
                a_hi[3] = __float_as_uint(ws_hi[r1 + 8]);
                a_lo[0] = __float_as_uint(ws_lo[r0]);
                a_lo[1] = __float_as_uint(ws_lo[r0 + 8]);
                a_lo[2] = __float_as_uint(ws_lo[r1]);
                a_lo[3] = __float_as_uint(ws_lo[r1 + 8]);
            }
            int hrow0 = (ccb + tig) * HS_STR;
            int hrow1 = (ccb + tig + 4) * HS_STR;
#pragma unroll
            for (int nf = 0; nf < 6; nf++) {
                int ncol = nb0 + nf * 8 + gid + kq;
                unsigned b_hi0 = __float_as_uint(hs_hi[hrow0 + ncol]);
                unsigned b_hi1 = __float_as_uint(hs_hi[hrow1 + ncol]);
                unsigned b_lo0 = __float_as_uint(hs_lo[hrow0 + ncol]);
                unsigned b_lo1 = __float_as_uint(hs_lo[hrow1 + ncol]);
                mma8(acc[nf], a_hi, b_hi0, b_hi1);
                mma8(acc[nf], a_hi, b_lo0, b_lo1);
                mma8(acc[nf], a_lo, b_hi0, b_hi1);
            }
        }
    }
    __syncthreads();
    // D fragments -> smem (exchange for cross-thread pooling)
#pragma unroll
    for (int nf = 0; nf < 6; nf++) {
        int col = nb0 + nf * 8 + tig * 2;
        sdout[(obase + gid) * SD_STR + col]     = acc[nf][0];
        sdout[(obase + gid) * SD_STR + col + 1] = acc[nf][1];
        sdout[(obase + gid + 8) * SD_STR + col]     = acc[nf][2];
        sdout[(obase + gid + 8) * SD_STR + col + 1] = acc[nf][3];
    }
    __syncthreads();
    // maxpool(3,3) + BN + ReLU -> g_h2
    float* h2b = g_h2 + (size_t)b * O2 * P2;
    for (int idx = tid; idx < 64 * 32; idx += 256) {
        int o = idx >> 5, j = idx & 31;
        int jg = j0 + j;
        if (jg < P2) {
            const float* r = sdout + o * SD_STR + 3 * j;
            float S = Ss[o], T = Ts[o];
            float a0 = r[0] * S + T;
            float a1 = r[1] * S + T;
            float a2 = r[2] * S + T;
            h2b[o * P2 + jg] = fmaxf(fmaxf(fmaxf(a0, a1), a2), 0.f);
        }
    }
}

// ============================================================
// Kernel 3: conv3(k3, 64ch) + BN + maxpool(3,2) + ReLU -> g_h3
// ============================================================
__global__ void k_conv3(const float* __restrict__ w, const float* __restrict__ cb,
                        const float* __restrict__ g, const float* __restrict__ be,
                        const float* __restrict__ m, const float* __restrict__ v) {
    __shared__ float hs[64][51];
    __shared__ float ws[96][65];
    __shared__ float Ss[O3], Ts[O3];
    int b = blockIdx.y;
    int j0 = blockIdx.x * 24;
    int tid = threadIdx.x;
    if (tid < O3) {
        float s = g[tid] * rsqrtf(v[tid] + EPS_BN);
        Ss[tid] = s;
        Ts[tid] = (cb[tid] - m[tid]) * s + be[tid];
    }
    const float* h2b = g_h2 + (size_t)b * O2 * P2;
    for (int idx = tid; idx < 64 * 51; idx += 256) {
        int cc = idx / 51, p = idx - cc * 51;
        hs[cc][p] = h2b[cc * P2 + 2 * j0 + p];
    }
    int o = tid & 63;
    int jg = tid >> 6;
    int lb = jg * 12;

    float acc[13];
#pragma unroll
    for (int i = 0; i < 13; i++) acc[i] = 0.f;

    for (int c0 = 0; c0 < 64; c0 += 32) {
        __syncthreads();
        for (int idx = tid; idx < 64 * 96; idx += 256) {
            int oo = idx / 96, r = idx - oo * 96;
            ws[r][oo] = w[oo * 192 + c0 * 3 + r];
        }
        __syncthreads();
#pragma unroll 1
        for (int cc = 0; cc < 32; cc++) {
            float wr[3];
#pragma unroll
            for (int k = 0; k < 3; k++) wr[k] = ws[cc * 3 + k][o];
            float h[15];
#pragma unroll
            for (int p = 0; p < 15; p++) h[p] = hs[c0 + cc][lb + p];
#pragma unroll
            for (int l = 0; l < 13; l++) {
                float s = acc[l];
#pragma unroll
                for (int k = 0; k < 3; k++) s += h[l + k] * wr[k];
                acc[l] = s;
            }
        }
    }
    float S = Ss[o], T = Ts[o];
    float* h3b = g_h3 + (size_t)b * O3 * P3;
#pragma unroll
    for (int jj = 0; jj < 6; jj++) {
        int jglob = j0 + jg * 6 + jj;
        float a0 = acc[2 * jj] * S + T;
        float a1 = acc[2 * jj + 1] * S + T;
        float a2 = acc[2 * jj + 2] * S + T;
        h3b[o * P3 + jglob] = fmaxf(fmaxf(fmaxf(a0, a1), a2), 0.f);
    }
}

// ============================================================
// Kernel 4: fc1 split-K tiled GEMM: out[256,48] = h3 @ W^T, 28 K-splits.
// ============================================================
__global__ void k_fc1gemm(const float* __restrict__ w) {
    __shared__ float hsm[32][65];
    __shared__ float wsm[48][65];
    int bt = blockIdx.x * 32;
    int ks = blockIdx.y;
    int t = threadIdx.x;
    int tx = t & 15;
    int ty = t >> 4;
    float acc[2][3] = {};
    int kbase = ks * FC_KC;
#pragma unroll 1
    for (int kk = 0; kk < FC_KC; kk += 64) {
        __syncthreads();
        for (int idx = t; idx < 32 * 16; idx += 256) {
            int r = idx >> 4, c4 = (idx & 15) * 4;
            float4 vv = *(const float4*)(g_h3 + (size_t)(bt + r) * FC_IN + kbase + kk + c4);
            hsm[r][c4] = vv.x; hsm[r][c4 + 1] = vv.y; hsm[r][c4 + 2] = vv.z; hsm[r][c4 + 3] = vv.w;
        }
        for (int idx = t; idx < 48 * 16; idx += 256) {
            int r = idx >> 4, c4 = (idx & 15) * 4;
            float4 vv = *(const float4*)(w + (size_t)r * FC_IN + kbase + kk + c4);
            wsm[r][c4] = vv.x; wsm[r][c4 + 1] = vv.y; wsm[r][c4 + 2] = vv.z; wsm[r][c4 + 3] = vv.w;
        }
        __syncthreads();
#pragma unroll 8
        for (int k = 0; k < 64; k++) {
            float h0 = hsm[2 * ty][k], h1 = hsm[2 * ty + 1][k];
            float w0 = wsm[3 * tx][k], w1 = wsm[3 * tx + 1][k], w2 = wsm[3 * tx + 2][k];
            acc[0][0] += h0 * w0; acc[0][1] += h0 * w1; acc[0][2] += h0 * w2;
            acc[1][0] += h1 * w0; acc[1][1] += h1 * w1; acc[1][2] += h1 * w2;
        }
    }
#pragma unroll
    for (int i = 0; i < 2; i++)
#pragma unroll
        for (int j = 0; j < 3; j++)
            g_fc1p[ks][bt + 2 * ty + i][3 * tx + j] = acc[i][j];
}

// ============================================================
// Kernel 5: reduce fc1 partials (+bias,ReLU) -> fc2 -> fc3 -> fc4 -> tanh
//           -> A = theta @ basis^T. One block, thread = batch.
// ============================================================
__global__ void k_fchead(const float* __restrict__ b1,
                         const float* __restrict__ w2, const float* __restrict__ b2,
                         const float* __restrict__ w3, const float* __restrict__ b3,
                         const float* __restrict__ w4, const float* __restrict__ b4,
                         const float* __restrict__ basis) {
    __shared__ float s2[32 * 48], sb2[32], s3[16 * 32], sb3[16], s4[5 * 16], sb4[5], sbas[60], sb1[48];
    int t = threadIdx.x;
    for (int i = t; i < 1536; i += 256) s2[i] = w2[i];
    for (int i = t; i < 512; i += 256) s3[i] = w3[i];
    if (t < 80) s4[t] = w4[t];
    if (t < 48) sb1[t] = b1[t];
    if (t < 32) sb2[t] = b2[t];
    if (t < 16) sb3[t] = b3[t];
    if (t < 5)  sb4[t] = b4[t];
    if (t < 60) sbas[t] = basis[t];
    __syncthreads();
    int b = t;
    float x1[48];
#pragma unroll
    for (int i = 0; i < 48; i++) {
        float s = sb1[i];
#pragma unroll
        for (int ks = 0; ks < FC_NS; ks++) s += g_fc1p[ks][b][i];
        x1[i] = fmaxf(s, 0.f);
    }
    float x2[32];
#pragma unroll
    for (int o = 0; o < 32; o++) {
        float s = sb2[o];
#pragma unroll
        for (int i = 0; i < 48; i++) s += x1[i] * s2[o * 48 + i];
        x2[o] = fmaxf(s, 0.f);
    }
    float x3[16];
#pragma unroll
    for (int o = 0; o < 16; o++) {
        float s = sb3[o];
#pragma unroll
        for (int i = 0; i < 32; i++) s += x2[i] * s3[o * 32 + i];
        x3[o] = fmaxf(s, 0.f);
    }
    float th[5];
#pragma unroll
    for (int o = 0; o < 5; o++) {
        float s = sb4[o];
#pragma unroll
        for (int i = 0; i < 16; i++) s += x3[i] * s4[o * 16 + i];
        th[o] = tanhf(s);
    }
#pragma unroll
    for (int r = 0; r < 12; r++) {
        float s = 0.f;
#pragma unroll
        for (int jq = 0; jq < 5; jq++) s += th[jq] * sbas[r * 5 + jq];
        g_A[b * 12 + r] = s;
    }
}

// ============================================================
// Kernel 6: exact CPAB integration of the grid + linear interpolation of x.
// ============================================================
__global__ void k_warp(const float* __restrict__ x, float* __restrict__ out) {
    __shared__ float a_s[6], b_s[6];
    int b = blockIdx.y;
    if (threadIdx.x < 12) {
        float val = g_A[b * 12 + threadIdx.x];
        if (threadIdx.x & 1) b_s[threadIdx.x >> 1] = val;
        else                 a_s[threadIdx.x >> 1] = val;
    }
    __syncthreads();
    int i = blockIdx.x * 256 + threadIdx.x;

    float xt = (float)i * (1.0f / 2047.0f);
    float t = 1.0f;
#pragma unroll 1
    for (int it = 0; it < 7; it++) {          // NC + 1 iterations
        int c = (int)floorf(xt * 6.0f);
        c = max(0, min(c, 5));
        float a = a_s[c], bb = b_s[c];
        float vv = a * xt + bb;
        float xbn = (vv >= 0.f) ? (float)(c + 1) / 6.0f : (float)c / 6.0f;
        bool big = fabsf(a) > 1e-8f;
        float a_sv = big ? a : 1.0f;
        float z  = xt  + bb / a_sv;
        float zb = xbn + bb / a_sv;
        float zden = (fabsf(z) > 1e-12f) ? z : 1e-12f;
        float ratio = zb / zden;
        float t_exp = logf(fmaxf(ratio, 1e-12f)) / a_sv;
        float v_sv = (fabsf(vv) > 1e-12f) ? vv : 1.0f;
        float t_lin = (xbn - xt) / v_sv;
        float thit = big ? t_exp : t_lin;
        bool valid = (fabsf(vv) > 1e-12f) && (thit > 0.f) && ((big ? ratio : 1.0f) > 0.f);
        if (!valid) thit = INFINITY;
        float tau = fminf(t, thit);
        float xn = big ? (z * expf(a * tau) - (z - xt)) : (xt + bb * tau);
        bool hit = (thit <= t);
        float nudge = (vv >= 0.f) ? 1e-6f : -1e-6f;
        xt = hit ? (xbn + nudge) : xn;
        xt = fminf(fmaxf(xt, 0.f), 1.f);
        t = fmaxf(t - tau, 0.f);
    }
    float p = fminf(fmaxf(xt, 0.f), 1.f) * 2047.0f;
    int x0 = (int)floorf(p);
    x0 = max(0, min(x0, 2046));
    float wgt = p - (float)x0;
    const float* xb = x + (size_t)b * NCH * SIG_LEN;
    float* ob = out + (size_t)b * NCH * SIG_LEN;
#pragma unroll
    for (int cch = 0; cch < NCH; cch++) {
        float d0 = xb[cch * SIG_LEN + x0];
        float d1 = xb[cch * SIG_LEN + x0 + 1];
        ob[cch * SIG_LEN + i] = d0 * (1.0f - wgt) + d1 * wgt;
    }
}

// ============================================================
extern "C" void kernel_launch(void* const* d_in, const int* in_sizes, int n_in,
                              void* d_out, int out_size) {
    const float* x       = (const float*)d_in[0];
    const float* c1w     = (const float*)d_in[1];
    const float* c1b     = (const float*)d_in[2];
    const float* bn1g    = (const float*)d_in[3];
    const float* bn1b    = (const float*)d_in[4];
    const float* bn1m    = (const float*)d_in[5];
    const float* bn1v    = (const float*)d_in[6];
    const float* c2w     = (const float*)d_in[7];
    const float* c2b     = (const float*)d_in[8];
    const float* bn2g    = (const float*)d_in[9];
    const float* bn2b    = (const float*)d_in[10];
    const float* bn2m    = (const float*)d_in[11];
    const float* bn2v    = (const float*)d_in[12];
    const float* c3w     = (const float*)d_in[13];
    const float* c3b     = (const float*)d_in[14];
    const float* bn3g    = (const float*)d_in[15];
    const float* bn3b    = (const float*)d_in[16];
    const float* bn3m    = (const float*)d_in[17];
    const float* bn3v    = (const float*)d_in[18];
    const float* fc1w    = (const float*)d_in[19];
    const float* fc1b    = (const float*)d_in[20];
    const float* fc2w    = (const float*)d_in[21];
    const float* fc2b    = (const float*)d_in[22];
    const float* fc3w    = (const float*)d_in[23];
    const float* fc3b    = (const float*)d_in[24];
    const float* fc4w    = (const float*)d_in[25];
    const float* fc4b    = (const float*)d_in[26];
    const float* basis   = (const float*)d_in[27];
    float* out = (float*)d_out;

    const int smem_bytes = SMEM_FLOATS * (int)sizeof(float);   // ~84 KB
    cudaFuncSetAttribute(k_conv2tc, cudaFuncAttributeMaxDynamicSharedMemorySize, smem_bytes);

    k_conv1<<<dim3((P1 + 127) / 128, BATCH), 128>>>(x, c1w, c1b, bn1g, bn1b, bn1m, bn1v);
    k_conv2tc<<<dim3((P2 + 31) / 32, BATCH), 256, smem_bytes>>>(c2w, c2b, bn2g, bn2b, bn2m, bn2v);
    k_conv3<<<dim3(P3 / 24, BATCH), 256>>>(c3w, c3b, bn3g, bn3b, bn3m, bn3v);
    k_fc1gemm<<<dim3(8, FC_NS), 256>>>(fc1w);
    k_fchead<<<1, 256>>>(fc1b, fc2w, fc2b, fc3w, fc3b, fc4w, fc4b, basis);
    k_warp<<<dim3(SIG_LEN / 256, BATCH), 256>>>(x, out);
}

// round 8
// speedup vs baseline: 1.0035x; 1.0035x over previous
#include <cuda_runtime.h>
#include <cuda_bf16.h>
#include <math.h>

// ---------------- problem constants ----------------
#define BATCH 256
#define SIG_LEN 2048
#define NCH 3
#define O1 128
#define P1 1022          // conv1(k3) -> 2046, pool k3 s2 -> 1022
#define O2 64
#define P2 339           // conv2(k5) -> 1018, pool k3 s3 -> 339
#define O3 64
#define P3 168           // conv3(k3) -> 337, pool k3 s2 -> 168
#define FC_IN 10752      // 64*168
#define EPS_BN 1e-5f
#define FC_NS 28
#define FC_KC 384        // FC_IN / FC_NS

// conv2-TC smem layout (floats)
#define WS_STR 72        // 72 % 32 == 8 -> conflict-free A-frag loads
#define HS_STR 104       // 104 % 32 == 8 -> conflict-free B-frag loads
#define SD_STR 97
#define OFF_WSHI 0
#define OFF_WSLO (80 * WS_STR)
#define OFF_HSHI (2 * 80 * WS_STR)
#define OFF_HSLO (2 * 80 * WS_STR + 16 * HS_STR)
#define OFF_SD   (2 * 80 * WS_STR + 2 * 16 * HS_STR)
#define SMEM_FLOATS (OFF_SD + 64 * SD_STR)

// ---------------- device scratch (no allocations allowed) ----------------
__device__ float g_h1[(size_t)BATCH * O1 * P1];   // 134 MB
__device__ float g_h2[(size_t)BATCH * O2 * P2];   // 22 MB
__device__ float g_h3[(size_t)BATCH * O3 * P3];   // 11 MB
__device__ float g_fc1p[FC_NS][BATCH][48];
__device__ float g_A[BATCH * 12];

// ---------------- tf32 helpers ----------------
__device__ __forceinline__ unsigned f2tf32(float x) {
    unsigned r; asm("cvt.rna.tf32.f32 %0, %1;" : "=r"(r) : "f"(x)); return r;
}
__device__ __forceinline__ void split_tf32(float x, float& hi, float& lo) {
    unsigned h = f2tf32(x);
    hi = __uint_as_float(h);
    lo = __uint_as_float(f2tf32(x - hi));
}
__device__ __forceinline__ void mma8(float* d, const unsigned* a, unsigned b0, unsigned b1) {
    asm volatile(
        "mma.sync.aligned.m16n8k8.row.col.f32.tf32.tf32.f32 "
        "{%0,%1,%2,%3}, {%4,%5,%6,%7}, {%8,%9}, {%0,%1,%2,%3};"
        : "+f"(d[0]), "+f"(d[1]), "+f"(d[2]), "+f"(d[3])
        : "r"(a[0]), "r"(a[1]), "r"(a[2]), "r"(a[3]), "r"(b0), "r"(b1));
}

// ============================================================
// Kernel 1: conv1(k3) + BN + maxpool(3,2) + ReLU  -> g_h1
// ============================================================
__global__ void k_conv1(const float* __restrict__ x, const float* __restrict__ w,
                        const float* __restrict__ cb, const float* __restrict__ g,
                        const float* __restrict__ be, const float* __restrict__ m,
                        const float* __restrict__ v) {
    __shared__ float ws[O1 * 9];
    __shared__ float Ss[O1], Ts[O1];
    int b = blockIdx.y;
    int tid = threadIdx.x;
    for (int i = tid; i < O1 * 9; i += 128) ws[i] = w[i];
    if (tid < O1) {
        float s = g[tid] * rsqrtf(v[tid] + EPS_BN);
        Ss[tid] = s;
        Ts[tid] = (cb[tid] - m[tid]) * s + be[tid];
    }
    __syncthreads();
    int j = blockIdx.x * 128 + tid;
    if (j >= P1) return;

    const float* xb = x + (size_t)b * NCH * SIG_LEN;
    float xv[3][5];
#pragma unroll
    for (int c = 0; c < 3; c++)
#pragma unroll
        for (int k = 0; k < 5; k++)
            xv[c][k] = xb[c * SIG_LEN + 2 * j + k];

    float* h1 = g_h1 + (size_t)b * O1 * P1;
#pragma unroll 4
    for (int o = 0; o < O1; o++) {
        const float* wo = ws + o * 9;
        float y0 = 0.f, y1 = 0.f, y2 = 0.f;
#pragma unroll
        for (int c = 0; c < 3; c++) {
#pragma unroll
            for (int k = 0; k < 3; k++) {
                float wv = wo[c * 3 + k];
                y0 += xv[c][k] * wv;
                y1 += xv[c][k + 1] * wv;
                y2 += xv[c][k + 2] * wv;
            }
        }
        float S = Ss[o], T = Ts[o];
        float r = fmaxf(fmaxf(y0 * S + T, y1 * S + T), y2 * S + T);
        h1[(size_t)o * P1 + j] = fmaxf(r, 0.f);
    }
}

// ============================================================
// Kernel 2: conv2 via 3xTF32 tensor-core implicit GEMM.
// Block = (b, 32 pooled j) = 96 pre-pool positions (pool s3: non-overlap).
// M=64 (o), N=96, K=640 (c*5+k, ordered kk = k*16+cc per 16-c chunk).
// 8 warps: warp = (otile 0..3) x (nhalf 0..1); warp tile M16 x N48.
// 3 MMA passes per frag: Ahi*Bhi + Ahi*Blo + Alo*Bhi (split-fp32 precision).
// Epilogue: D -> smem -> maxpool(3,3) + BN + ReLU -> g_h2.
// ============================================================
__global__ void k_conv2tc(const float* __restrict__ w, const float* __restrict__ cb,
                          const float* __restrict__ g, const float* __restrict__ be,
                          const float* __restrict__ m, const float* __restrict__ v) {
    extern __shared__ float sm[];
    float* ws_hi = sm + OFF_WSHI;   // [80][WS_STR]
    float* ws_lo = sm + OFF_WSLO;
    float* hs_hi = sm + OFF_HSHI;   // [16][HS_STR]
    float* hs_lo = sm + OFF_HSLO;
    float* sdout = sm + OFF_SD;     // [64][SD_STR]
    __shared__ float Ss[O2], Ts[O2];

    int b = blockIdx.y;
    int j0 = blockIdx.x * 32;
    int tid = threadIdx.x;
    if (tid < O2) {
        float s = g[tid] * rsqrtf(v[tid] + EPS_BN);
        Ss[tid] = s;
        Ts[tid] = (cb[tid] - m[tid]) * s + be[tid];
    }
    int lane = tid & 31, wid = tid >> 5;
    int gid = lane >> 2, tig = lane & 3;
    int obase = (wid & 3) * 16;
    int nb0 = (wid >> 2) * 48;

    float acc[6][4];
#pragma unroll
    for (int i = 0; i < 6; i++)
#pragma unroll
        for (int jq = 0; jq < 4; jq++) acc[i][jq] = 0.f;

    const float* h1b = g_h1 + (size_t)b * O1 * P1;
    int gbase = 3 * j0;

    for (int c0 = 0; c0 < O1; c0 += 16) {
        __syncthreads();
        // stage h1 tile, split hi/lo tf32 at fill time
        for (int idx = tid; idx < 16 * 100; idx += 256) {
            int cc = idx / 100, p = idx - cc * 100;
            int gp = gbase + p;
            float xv = (gp < P1) ? h1b[(size_t)(c0 + cc) * P1 + gp] : 0.f;
            float hf, lf; split_tf32(xv, hf, lf);
            hs_hi[cc * HS_STR + p] = hf;
            hs_lo[cc * HS_STR + p] = lf;
        }
        // stage weights transposed [kk = k*16+cc][o], split hi/lo
        for (int idx = tid; idx < 80 * 64; idx += 256) {
            int kk = idx >> 6, o = idx & 63;
            int k = kk >> 4, cc = kk & 15;
            float xv = w[o * 640 + (c0 + cc) * 5 + k];
            float hf, lf; split_tf32(xv, hf, lf);
            ws_hi[kk * WS_STR + o] = hf;
            ws_lo[kk * WS_STR + o] = lf;
        }
        __syncthreads();
#pragma unroll
        for (int s = 0; s < 10; s++) {
            int kkb = s * 8;
            int kq = s >> 1;            // conv tap for all 8 K-rows of this step
            int ccb = (s & 1) * 8;      // channel base within chunk
            unsigned a_hi[4], a_lo[4];
            {
                int r0 = (kkb + tig) * WS_STR + obase + gid;
                int r1 = (kkb + tig + 4) * WS_STR + obase + gid;
                a_hi[0] = __float_as_uint(ws_hi[r0]);
                a_hi[1] = __float_as_uint(ws_hi[r0 + 8]);
                a_hi[2] = __float_as_uint(ws_hi[r1]);
                a_hi[3] = __float_as_uint(ws_hi[r1 + 8]);
                a_lo[0] = __float_as_uint(ws_lo[r0]);
                a_lo[1] = __float_as_uint(ws_lo[r0 + 8]);
                a_lo[2] = __float_as_uint(ws_lo[r1]);
                a_lo[3] = __float_as_uint(ws_lo[r1 + 8]);
            }
            int hrow0 = (ccb + tig) * HS_STR;
            int hrow1 = (ccb + tig + 4) * HS_STR;
#pragma unroll
            for (int nf = 0; nf < 6; nf++) {
                int ncol = nb0 + nf * 8 + gid + kq;
                unsigned b_hi0 = __float_as_uint(hs_hi[hrow0 + ncol]);
                unsigned b_hi1 = __float_as_uint(hs_hi[hrow1 + ncol]);
                unsigned b_lo0 = __float_as_uint(hs_lo[hrow0 + ncol]);
                unsigned b_lo1 = __float_as_uint(hs_lo[hrow1 + ncol]);
                mma8(acc[nf], a_hi, b_hi0, b_hi1);
                mma8(acc[nf], a_hi, b_lo0, b_lo1);
                mma8(acc[nf], a_lo, b_hi0, b_hi1);
            }
        }
    }
    __syncthreads();
    // D fragments -> smem (exchange for cross-thread pooling)
#pragma unroll
    for (int nf = 0; nf < 6; nf++) {
        int col = nb0 + nf * 8 + tig * 2;
        sdout[(obase + gid) * SD_STR + col]     = acc[nf][0];
        sdout[(obase + gid) * SD_STR + col + 1] = acc[nf][1];
        sdout[(obase + gid + 8) * SD_STR + col]     = acc[nf][2];
        sdout[(obase + gid + 8) * SD_STR + col + 1] = acc[nf][3];
    }
    __syncthreads();
    // maxpool(3,3) + BN + ReLU -> g_h2
    float* h2b = g_h2 + (size_t)b * O2 * P2;
    for (int idx = tid; idx < 64 * 32; idx += 256) {
        int o = idx >> 5, j = idx & 31;
        int jg = j0 + j;
        if (jg < P2) {
            const float* r = sdout + o * SD_STR + 3 * j;
            float S = Ss[o], T = Ts[o];
            float a0 = r[0] * S + T;
            float a1 = r[1] * S + T;
            float a2 = r[2] * S + T;
            h2b[o * P2 + jg] = fmaxf(fmaxf(fmaxf(a0, a1), a2), 0.f);
        }
    }
}

// ============================================================
// Kernel 3: conv3(k3, 64ch) + BN + maxpool(3,2) + ReLU -> g_h3
// ============================================================
__global__ void k_conv3(const float* __restrict__ w, const float* __restrict__ cb,
                        const float* __restrict__ g, const float* __restrict__ be,
                        const float* __restrict__ m, const float* __restrict__ v) {
    __shared__ float hs[64][51];
    __shared__ float ws[96][65];
    __shared__ float Ss[O3], Ts[O3];
    int b = blockIdx.y;
    int j0 = blockIdx.x * 24;
    int tid = threadIdx.x;
    if (tid < O3) {
        float s = g[tid] * rsqrtf(v[tid] + EPS_BN);
        Ss[tid] = s;
        Ts[tid] = (cb[tid] - m[tid]) * s + be[tid];
    }
    const float* h2b = g_h2 + (size_t)b * O2 * P2;
    for (int idx = tid; idx < 64 * 51; idx += 256) {
        int cc = idx / 51, p = idx - cc * 51;
        hs[cc][p] = h2b[cc * P2 + 2 * j0 + p];
    }
    int o = tid & 63;
    int jg = tid >> 6;
    int lb = jg * 12;

    float acc[13];
#pragma unroll
    for (int i = 0; i < 13; i++) acc[i] = 0.f;

    for (int c0 = 0; c0 < 64; c0 += 32) {
        __syncthreads();
        for (int idx = tid; idx < 64 * 96; idx += 256) {
            int oo = idx / 96, r = idx - oo * 96;
            ws[r][oo] = w[oo * 192 + c0 * 3 + r];
        }
        __syncthreads();
#pragma unroll 1
        for (int cc = 0; cc < 32; cc++) {
            float wr[3];
#pragma unroll
            for (int k = 0; k < 3; k++) wr[k] = ws[cc * 3 + k][o];
            float h[15];
#pragma unroll
            for (int p = 0; p < 15; p++) h[p] = hs[c0 + cc][lb + p];
#pragma unroll
            for (int l = 0; l < 13; l++) {
                float s = acc[l];
#pragma unroll
                for (int k = 0; k < 3; k++) s += h[l + k] * wr[k];
                acc[l] = s;
            }
        }
    }
    float S = Ss[o], T = Ts[o];
    float* h3b = g_h3 + (size_t)b * O3 * P3;
#pragma unroll
    for (int jj = 0; jj < 6; jj++) {
        int jglob = j0 + jg * 6 + jj;
        float a0 = acc[2 * jj] * S + T;
        float a1 = acc[2 * jj + 1] * S + T;
        float a2 = acc[2 * jj + 2] * S + T;
        h3b[o * P3 + jglob] = fmaxf(fmaxf(fmaxf(a0, a1), a2), 0.f);
    }
}

// ============================================================
// Kernel 4: fc1 split-K tiled GEMM: out[256,48] = h3 @ W^T, 28 K-splits.
// ============================================================
__global__ void k_fc1gemm(const float* __restrict__ w) {
    __shared__ float hsm[32][65];
    __shared__ float wsm[48][65];
    int bt = blockIdx.x * 32;
    int ks = blockIdx.y;
    int t = threadIdx.x;
    int tx = t & 15;
    int ty = t >> 4;
    float acc[2][3] = {};
    int kbase = ks * FC_KC;
#pragma unroll 1
    for (int kk = 0; kk < FC_KC; kk += 64) {
        __syncthreads();
        for (int idx = t; idx < 32 * 16; idx += 256) {
            int r = idx >> 4, c4 = (idx & 15) * 4;
            float4 vv = *(const float4*)(g_h3 + (size_t)(bt + r) * FC_IN + kbase + kk + c4);
            hsm[r][c4] = vv.x; hsm[r][c4 + 1] = vv.y; hsm[r][c4 + 2] = vv.z; hsm[r][c4 + 3] = vv.w;
        }
        for (int idx = t; idx < 48 * 16; idx += 256) {
            int r = idx >> 4, c4 = (idx & 15) * 4;
            float4 vv = *(const float4*)(w + (size_t)r * FC_IN + kbase + kk + c4);
            wsm[r][c4] = vv.x; wsm[r][c4 + 1] = vv.y; wsm[r][c4 + 2] = vv.z; wsm[r][c4 + 3] = vv.w;
        }
        __syncthreads();
#pragma unroll 8
        for (int k = 0; k < 64; k++) {
            float h0 = hsm[2 * ty][k], h1 = hsm[2 * ty + 1][k];
            float w0 = wsm[3 * tx][k], w1 = wsm[3 * tx + 1][k], w2 = wsm[3 * tx + 2][k];
            acc[0][0] += h0 * w0; acc[0][1] += h0 * w1; acc[0][2] += h0 * w2;
            acc[1][0] += h1 * w0; acc[1][1] += h1 * w1; acc[1][2] += h1 * w2;
        }
    }
#pragma unroll
    for (int i = 0; i < 2; i++)
#pragma unroll
        for (int j = 0; j < 3; j++)
            g_fc1p[ks][bt + 2 * ty + i][3 * tx + j] = acc[i][j];
}

// ============================================================
// Kernel 5: reduce fc1 partials (+bias,ReLU) -> fc2 -> fc3 -> fc4 -> tanh
//           -> A = theta @ basis^T. One block, thread = batch.
// ============================================================
__global__ void k_fchead(const float* __restrict__ b1,
                         const float* __restrict__ w2, const float* __restrict__ b2,
                         const float* __restrict__ w3, const float* __restrict__ b3,
                         const float* __restrict__ w4, const float* __restrict__ b4,
                         const float* __restrict__ basis) {
    __shared__ float s2[32 * 48], sb2[32], s3[16 * 32], sb3[16], s4[5 * 16], sb4[5], sbas[60], sb1[48];
    int t = threadIdx.x;
    for (int i = t; i < 1536; i += 256) s2[i] = w2[i];
    for (int i = t; i < 512; i += 256) s3[i] = w3[i];
    if (t < 80) s4[t] = w4[t];
    if (t < 48) sb1[t] = b1[t];
    if (t < 32) sb2[t] = b2[t];
    if (t < 16) sb3[t] = b3[t];
    if (t < 5)  sb4[t] = b4[t];
    if (t < 60) sbas[t] = basis[t];
    __syncthreads();
    int b = t;
    float x1[48];
#pragma unroll
    for (int i = 0; i < 48; i++) {
        float s = sb1[i];
#pragma unroll
        for (int ks = 0; ks < FC_NS; ks++) s += g_fc1p[ks][b][i];
        x1[i] = fmaxf(s, 0.f);
    }
    float x2[32];
#pragma unroll
    for (int o = 0; o < 32; o++) {
        float s = sb2[o];
#pragma unroll
        for (int i = 0; i < 48; i++) s += x1[i] * s2[o * 48 + i];
        x2[o] = fmaxf(s, 0.f);
    }
    float x3[16];
#pragma unroll
    for (int o = 0; o < 16; o++) {
        float s = sb3[o];
#pragma unroll
        for (int i = 0; i < 32; i++) s += x2[i] * s3[o * 32 + i];
        x3[o] = fmaxf(s, 0.f);
    }
    float th[5];
#pragma unroll
    for (int o = 0; o < 5; o++) {
        float s = sb4[o];
#pragma unroll
        for (int i = 0; i < 16; i++) s += x3[i] * s4[o * 16 + i];
        th[o] = tanhf(s);
    }
#pragma unroll
    for (int r = 0; r < 12; r++) {
        float s = 0.f;
#pragma unroll
        for (int jq = 0; jq < 5; jq++) s += th[jq] * sbas[r * 5 + jq];
        g_A[b * 12 + r] = s;
    }
}

// ============================================================
// Kernel 6: exact CPAB integration of the grid + linear interpolation of x.
// ============================================================
__global__ void k_warp(const float* __restrict__ x, float* __restrict__ out) {
    __shared__ float a_s[6], b_s[6];
    int b = blockIdx.y;
    if (threadIdx.x < 12) {
        float val = g_A[b * 12 + threadIdx.x];
        if (threadIdx.x & 1) b_s[threadIdx.x >> 1] = val;
        else                 a_s[threadIdx.x >> 1] = val;
    }
    __syncthreads();
    int i = blockIdx.x * 256 + threadIdx.x;

    float xt = (float)i * (1.0f / 2047.0f);
    float t = 1.0f;
#pragma unroll 1
    for (int it = 0; it < 7; it++) {          // NC + 1 iterations
        int c = (int)floorf(xt * 6.0f);
        c = max(0, min(c, 5));
        float a = a_s[c], bb = b_s[c];
        float vv = a * xt + bb;
        float xbn = (vv >= 0.f) ? (float)(c + 1) / 6.0f : (float)c / 6.0f;
        bool big = fabsf(a) > 1e-8f;
        float a_sv = big ? a : 1.0f;
        float z  = xt  + bb / a_sv;
        float zb = xbn + bb / a_sv;
        float zden = (fabsf(z) > 1e-12f) ? z : 1e-12f;
        float ratio = zb / zden;
        float t_exp = logf(fmaxf(ratio, 1e-12f)) / a_sv;
        float v_sv = (fabsf(vv) > 1e-12f) ? vv : 1.0f;
        float t_lin = (xbn - xt) / v_sv;
        float thit = big ? t_exp : t_lin;
        bool valid = (fabsf(vv) > 1e-12f) && (thit > 0.f) && ((big ? ratio : 1.0f) > 0.f);
        if (!valid) thit = INFINITY;
        float tau = fminf(t, thit);
        float xn = big ? (z * expf(a * tau) - (z - xt)) : (xt + bb * tau);
        bool hit = (thit <= t);
        float nudge = (vv >= 0.f) ? 1e-6f : -1e-6f;
        xt = hit ? (xbn + nudge) : xn;
        xt = fminf(fmaxf(xt, 0.f), 1.f);
        t = fmaxf(t - tau, 0.f);
    }
    float p = fminf(fmaxf(xt, 0.f), 1.f) * 2047.0f;
    int x0 = (int)floorf(p);
    x0 = max(0, min(x0, 2046));
    float wgt = p - (float)x0;
    const float* xb = x + (size_t)b * NCH * SIG_LEN;
    float* ob = out + (size_t)b * NCH * SIG_LEN;
#pragma unroll
    for (int cch = 0; cch < NCH; cch++) {
        float d0 = xb[cch * SIG_LEN + x0];
        float d1 = xb[cch * SIG_LEN + x0 + 1];
        ob[cch * SIG_LEN + i] = d0 * (1.0f - wgt) + d1 * wgt;
    }
}

// ============================================================
extern "C" void kernel_launch(void* const* d_in, const int* in_sizes, int n_in,
                              void* d_out, int out_size) {
    const float* x       = (const float*)d_in[0];
    const float* c1w     = (const float*)d_in[1];
    const float* c1b     = (const float*)d_in[2];
    const float* bn1g    = (const float*)d_in[3];
    const float* bn1b    = (const float*)d_in[4];
    const float* bn1m    = (const float*)d_in[5];
    const float* bn1v    = (const float*)d_in[6];
    const float* c2w     = (const float*)d_in[7];
    const float* c2b     = (const float*)d_in[8];
    const float* bn2g    = (const float*)d_in[9];
    const float* bn2b    = (const float*)d_in[10];
    const float* bn2m    = (const float*)d_in[11];
    const float* bn2v    = (const float*)d_in[12];
    const float* c3w     = (const float*)d_in[13];
    const float* c3b     = (const float*)d_in[14];
    const float* bn3g    = (const float*)d_in[15];
    const float* bn3b    = (const float*)d_in[16];
    const float* bn3m    = (const float*)d_in[17];
    const float* bn3v    = (const float*)d_in[18];
    const float* fc1w    = (const float*)d_in[19];
    const float* fc1b    = (const float*)d_in[20];
    const float* fc2w    = (const float*)d_in[21];
    const float* fc2b    = (const float*)d_in[22];
    const float* fc3w    = (const float*)d_in[23];
    const float* fc3b    = (const float*)d_in[24];
    const float* fc4w    = (const float*)d_in[25];
    const float* fc4b    = (const float*)d_in[26];
    const float* basis   = (const float*)d_in[27];
    float* out = (float*)d_out;

    const int smem_bytes = SMEM_FLOATS * (int)sizeof(float);   // ~84 KB
    cudaFuncSetAttribute(k_conv2tc, cudaFuncAttributeMaxDynamicSharedMemorySize, smem_bytes);

    k_conv1<<<dim3((P1 + 127) / 128, BATCH), 128>>>(x, c1w, c1b, bn1g, bn1b, bn1m, bn1v);
    k_conv2tc<<<dim3((P2 + 31) / 32, BATCH), 256, smem_bytes>>>(c2w, c2b, bn2g, bn2b, bn2m, bn2v);
    k_conv3<<<dim3(P3 / 24, BATCH), 256>>>(c3w, c3b, bn3g, bn3b, bn3m, bn3v);
    k_fc1gemm<<<dim3(8, FC_NS), 256>>>(fc1w);
    k_fchead<<<1, 256>>>(fc1b, fc2w, fc2b, fc3w, fc3b, fc4w, fc4b, basis);
    k_warp<<<dim3(SIG_LEN / 256, BATCH), 256>>>(x, out);
}

// round 10
// speedup vs baseline: 1.4374x; 1.4325x over previous
#include <cuda_runtime.h>
#include <cuda_bf16.h>
#include <math.h>

// ---------------- problem constants ----------------
#define BATCH 256
#define SIG_LEN 2048
#define NCH 3
#define O1 128
#define P1 1022          // conv1(k3) -> 2046, pool k3 s2 -> 1022
#define O2 64
#define P2 339           // conv2(k5) -> 1018, pool k3 s3 -> 339
#define O3 64
#define P3 168           // conv3(k3) -> 337, pool k3 s2 -> 168
#define FC_IN 10752      // 64*168
#define EPS_BN 1e-5f
#define FC_NS 28
#define FC_KC 384        // FC_IN / FC_NS

// conv2-TC smem layout (floats)
#define WS_STR 72        // 72 % 32 == 8 -> conflict-free A-frag loads
#define HS_STR 104       // 104 % 32 == 8 -> conflict-free B-frag loads
#define SD_STR 97
#define OFF_WSHI 0
#define OFF_WSLO (80 * WS_STR)
#define OFF_HSHI (2 * 80 * WS_STR)
#define OFF_HSLO (2 * 80 * WS_STR + 16 * HS_STR)
#define OFF_SD   (2 * 80 * WS_STR + 2 * 16 * HS_STR)
#define SMEM_FLOATS (OFF_SD + 64 * SD_STR)

// ---------------- device scratch (no allocations allowed) ----------------
__device__ float g_h1[(size_t)BATCH * O1 * P1];   // 134 MB
__device__ float g_h2[(size_t)BATCH * O2 * P2];   // 22 MB
__device__ float g_h3[(size_t)BATCH * O3 * P3];   // 11 MB
__device__ float g_fc1p[FC_NS][BATCH][48];
__device__ float g_A[BATCH * 12];
__device__ float g_w2s[2 * 8 * 80 * 64];          // pre-split conv2 weights [hi/lo][chunk][kk][o]

// ---------------- tf32 helpers ----------------
__device__ __forceinline__ unsigned f2tf32(float x) {
    unsigned r; asm("cvt.rna.tf32.f32 %0, %1;" : "=r"(r) : "f"(x)); return r;
}
__device__ __forceinline__ void split_tf32(float x, float& hi, float& lo) {
    unsigned h = f2tf32(x);
    hi = __uint_as_float(h);
    lo = __uint_as_float(f2tf32(x - hi));
}
__device__ __forceinline__ void mma8(float* d, const unsigned* a, unsigned b0, unsigned b1) {
    asm volatile(
        "mma.sync.aligned.m16n8k8.row.col.f32.tf32.tf32.f32 "
        "{%0,%1,%2,%3}, {%4,%5,%6,%7}, {%8,%9}, {%0,%1,%2,%3};"
        : "+f"(d[0]), "+f"(d[1]), "+f"(d[2]), "+f"(d[3])
        : "r"(a[0]), "r"(a[1]), "r"(a[2]), "r"(a[3]), "r"(b0), "r"(b1));
}

// ============================================================
// Dummy kernels: shift k_conv2tc into the ncu-profiled 4th launch slot.
// ============================================================
__global__ void k_nop1() {}
__global__ void k_nop2() {}

// ============================================================
// Kernel 0: pre-split conv2 weights into hi/lo tf32 planes,
// laid out [chunk][kk=k*16+cc][o] so conv2 staging is a raw copy.
// ============================================================
__global__ void k_wsplit(const float* __restrict__ w) {
    int idx = blockIdx.x * 256 + threadIdx.x;
    if (idx >= 8 * 80 * 64) return;
    int o = idx & 63;
    int kk = (idx >> 6) % 80;
    int chunk = idx / 5120;
    int k = kk >> 4, cc = kk & 15;
    float xv = w[o * 640 + (chunk * 16 + cc) * 5 + k];
    float hf, lf; split_tf32(xv, hf, lf);
    g_w2s[idx] = hf;
    g_w2s[8 * 80 * 64 + idx] = lf;
}

// ============================================================
// Kernel 1: conv1(k3) + BN + maxpool(3,2) + ReLU  -> g_h1
// ============================================================
__global__ void k_conv1(const float* __restrict__ x, const float* __restrict__ w,
                        const float* __restrict__ cb, const float* __restrict__ g,
                        const float* __restrict__ be, const float* __restrict__ m,
                        const float* __restrict__ v) {
    __shared__ float ws[O1 * 9];
    __shared__ float Ss[O1], Ts[O1];
    int b = blockIdx.y;
    int tid = threadIdx.x;
    for (int i = tid; i < O1 * 9; i += 128) ws[i] = w[i];
    if (tid < O1) {
        float s = g[tid] * rsqrtf(v[tid] + EPS_BN);
        Ss[tid] = s;
        Ts[tid] = (cb[tid] - m[tid]) * s + be[tid];
    }
    __syncthreads();
    int j = blockIdx.x * 128 + tid;
    if (j >= P1) return;

    const float* xb = x + (size_t)b * NCH * SIG_LEN;
    float xv[3][5];
#pragma unroll
    for (int c = 0; c < 3; c++)
#pragma unroll
        for (int k = 0; k < 5; k++)
            xv[c][k] = xb[c * SIG_LEN + 2 * j + k];

    float* h1 = g_h1 + (size_t)b * O1 * P1;
#pragma unroll 4
    for (int o = 0; o < O1; o++) {
        const float* wo = ws + o * 9;
        float y0 = 0.f, y1 = 0.f, y2 = 0.f;
#pragma unroll
        for (int c = 0; c < 3; c++) {
#pragma unroll
            for (int k = 0; k < 3; k++) {
                float wv = wo[c * 3 + k];
                y0 += xv[c][k] * wv;
                y1 += xv[c][k + 1] * wv;
                y2 += xv[c][k + 2] * wv;
            }
        }
        float S = Ss[o], T = Ts[o];
        float r = fmaxf(fmaxf(y0 * S + T, y1 * S + T), y2 * S + T);
        h1[(size_t)o * P1 + j] = fmaxf(r, 0.f);
    }
}

// ============================================================
// Kernel 2: conv2 via 3xTF32 mma.sync implicit GEMM (R7 design +
// pre-split weights: staging is now pure float4 copies from g_w2s).
// Block = (b, 32 pooled j) = 96 pre-pool positions.
// M=64 (o), N=96, K=640 (kk = k*16+cc per 16-c chunk).
// 8 warps = (otile 0..3) x (nhalf 0..1); warp tile M16 x N48.
// Passes per frag: Ahi*Bhi + Ahi*Blo + Alo*Bhi.
// ============================================================
__global__ void k_conv2tc(const float* __restrict__ cb,
                          const float* __restrict__ g, const float* __restrict__ be,
                          const float* __restrict__ m, const float* __restrict__ v) {
    extern __shared__ float sm[];
    float* ws_hi = sm + OFF_WSHI;   // [80][WS_STR]
    float* ws_lo = sm + OFF_WSLO;
    float* hs_hi = sm + OFF_HSHI;   // [16][HS_STR]
    float* hs_lo = sm + OFF_HSLO;
    float* sdout = sm + OFF_SD;     // [64][SD_STR]
    __shared__ float Ss[O2], Ts[O2];

    int b = blockIdx.y;
    int j0 = blockIdx.x * 32;
    int tid = threadIdx.x;
    if (tid < O2) {
        float s = g[tid] * rsqrtf(v[tid] + EPS_BN);
        Ss[tid] = s;
        Ts[tid] = (cb[tid] - m[tid]) * s + be[tid];
    }
    int lane = tid & 31, wid = tid >> 5;
    int gid = lane >> 2, tig = lane & 3;
    int obase = (wid & 3) * 16;
    int nb0 = (wid >> 2) * 48;

    float acc[6][4];
#pragma unroll
    for (int i = 0; i < 6; i++)
#pragma unroll
        for (int jq = 0; jq < 4; jq++) acc[i][jq] = 0.f;

    const float* h1b = g_h1 + (size_t)b * O1 * P1;
    int gbase = 3 * j0;

    for (int chunk = 0; chunk < 8; chunk++) {
        int c0 = chunk * 16;
        __syncthreads();
        // stage h1 tile, split hi/lo tf32 at fill time (small: 1600 elems)
        for (int idx = tid; idx < 16 * 100; idx += 256) {
            int cc = idx / 100, p = idx - cc * 100;
            int gp = gbase + p;
            float xv = (gp < P1) ? h1b[(size_t)(c0 + cc) * P1 + gp] : 0.f;
            float hf, lf; split_tf32(xv, hf, lf);
            hs_hi[cc * HS_STR + p] = hf;
            hs_lo[cc * HS_STR + p] = lf;
        }
        // stage pre-split weights: raw float4 copies
        {
            const float4* srch = (const float4*)(g_w2s + chunk * 5120);
            const float4* srcl = (const float4*)(g_w2s + 8 * 80 * 64 + chunk * 5120);
            for (int q = tid; q < 1280; q += 256) {
                int row = q >> 4, o4 = (q & 15) * 4;
                float4 hv = srch[q];
                float4 lv = srcl[q];
                *(float4*)&ws_hi[row * WS_STR + o4] = hv;
                *(float4*)&ws_lo[row * WS_STR + o4] = lv;
            }
        }
        __syncthreads();
#pragma unroll
        for (int s = 0; s < 10; s++) {
            int kkb = s * 8;
            int kq = s >> 1;            // conv tap for this K-step
            int ccb = (s & 1) * 8;      // channel base within chunk
            unsigned a_hi[4], a_lo[4];
            {
                int r0 = (kkb + tig) * WS_STR + obase + gid;
                int r1 = (kkb + tig + 4) * WS_STR + obase + gid;
                a_hi[0] = __float_as_uint(ws_hi[r0]);
                a_hi[1] = __float_as_uint(ws_hi[r0 + 8]);
                a_hi[2] = __float_as_uint(ws_hi[r1]);
                a_hi[3] = __float_as_uint(ws_hi[r1 + 8]);
                a_lo[0] = __float_as_uint(ws_lo[r0]);
                a_lo[1] = __float_as_uint(ws_lo[r0 + 8]);
                a_lo[2] = __float_as_uint(ws_lo[r1]);
                a_lo[3] = __float_as_uint(ws_lo[r1 + 8]);
            }
            int hrow0 = (ccb + tig) * HS_STR;
            int hrow1 = (ccb + tig + 4) * HS_STR;
#pragma unroll
            for (int nf = 0; nf < 6; nf++) {
                int ncol = nb0 + nf * 8 + gid + kq;
                unsigned b_hi0 = __float_as_uint(hs_hi[hrow0 + ncol]);
                unsigned b_hi1 = __float_as_uint(hs_hi[hrow1 + ncol]);
                unsigned b_lo0 = __float_as_uint(hs_lo[hrow0 + ncol]);
                unsigned b_lo1 = __float_as_uint(hs_lo[hrow1 + ncol]);
                mma8(acc[nf], a_hi, b_hi0, b_hi1);
                mma8(acc[nf], a_hi, b_lo0, b_lo1);
                mma8(acc[nf], a_lo, b_hi0, b_hi1);
            }
        }
    }
    __syncthreads();
    // D fragments -> smem (exchange for cross-thread pooling)
#pragma unroll
    for (int nf = 0; nf < 6; nf++) {
        int col = nb0 + nf * 8 + tig * 2;
        sdout[(obase + gid) * SD_STR + col]     = acc[nf][0];
        sdout[(obase + gid) * SD_STR + col + 1] = acc[nf][1];
        sdout[(obase + gid + 8) * SD_STR + col]     = acc[nf][2];
        sdout[(obase + gid + 8) * SD_STR + col + 1] = acc[nf][3];
    }
    __syncthreads();
    // maxpool(3,3) + BN + ReLU -> g_h2
    float* h2b = g_h2 + (size_t)b * O2 * P2;
    for (int idx = tid; idx < 64 * 32; idx += 256) {
        int o = idx >> 5, j = idx & 31;
        int jg = j0 + j;
        if (jg < P2) {
            const float* r = sdout + o * SD_STR + 3 * j;
            float S = Ss[o], T = Ts[o];
            float a0 = r[0] * S + T;
            float a1 = r[1] * S + T;
            float a2 = r[2] * S + T;
            h2b[o * P2 + jg] = fmaxf(fmaxf(fmaxf(a0, a1), a2), 0.f);
        }
    }
}

// ============================================================
// Kernel 3: conv3(k3, 64ch) + BN + maxpool(3,2) + ReLU -> g_h3
// ============================================================
__global__ void k_conv3(const float* __restrict__ w, const float* __restrict__ cb,
                        const float* __restrict__ g, const float* __restrict__ be,
                        const float* __restrict__ m, const float* __restrict__ v) {
    __shared__ float hs[64][51];
    __shared__ float ws[96][65];
    __shared__ float Ss[O3], Ts[O3];
    int b = blockIdx.y;
    int j0 = blockIdx.x * 24;
    int tid = threadIdx.x;
    if (tid < O3) {
        float s = g[tid] * rsqrtf(v[tid] + EPS_BN);
        Ss[tid] = s;
        Ts[tid] = (cb[tid] - m[tid]) * s + be[tid];
    }
    const float* h2b = g_h2 + (size_t)b * O2 * P2;
    for (int idx = tid; idx < 64 * 51; idx += 256) {
        int cc = idx / 51, p = idx - cc * 51;
        hs[cc][p] = h2b[cc * P2 + 2 * j0 + p];
    }
    int o = tid & 63;
    int jg = tid >> 6;
    int lb = jg * 12;

    float acc[13];
#pragma unroll
    for (int i = 0; i < 13; i++) acc[i] = 0.f;

    for (int c0 = 0; c0 < 64; c0 += 32) {
        __syncthreads();
        for (int idx = tid; idx < 64 * 96; idx += 256) {
            int oo = idx / 96, r = idx - oo * 96;
            ws[r][oo] = w[oo * 192 + c0 * 3 + r];
        }
        __syncthreads();
#pragma unroll 1
        for (int cc = 0; cc < 32; cc++) {
            float wr[3];
#pragma unroll
            for (int k = 0; k < 3; k++) wr[k] = ws[cc * 3 + k][o];
            float h[15];
#pragma unroll
            for (int p = 0; p < 15; p++) h[p] = hs[c0 + cc][lb + p];
#pragma unroll
            for (int l = 0; l < 13; l++) {
                float s = acc[l];
#pragma unroll
                for (int k = 0; k < 3; k++) s += h[l + k] * wr[k];
                acc[l] = s;
            }
        }
    }
    float S = Ss[o], T = Ts[o];
    float* h3b = g_h3 + (size_t)b * O3 * P3;
#pragma unroll
    for (int jj = 0; jj < 6; jj++) {
        int jglob = j0 + jg * 6 + jj;
        float a0 = acc[2 * jj] * S + T;
        float a1 = acc[2 * jj + 1] * S + T;
        float a2 = acc[2 * jj + 2] * S + T;
        h3b[o * P3 + jglob] = fmaxf(fmaxf(fmaxf(a0, a1), a2), 0.f);
    }
}

// ============================================================
// Kernel 4: fc1 split-K tiled GEMM: out[256,48] = h3 @ W^T, 28 K-splits.
// ============================================================
__global__ void k_fc1gemm(const float* __restrict__ w) {
    __shared__ float hsm[32][65];
    __shared__ float wsm[48][65];
    int bt = blockIdx.x * 32;
    int ks = blockIdx.y;
    int t = threadIdx.x;
    int tx = t & 15;
    int ty = t >> 4;
    float acc[2][3] = {};
    int kbase = ks * FC_KC;
#pragma unroll 1
    for (int kk = 0; kk < FC_KC; kk += 64) {
        __syncthreads();
        for (int idx = t; idx < 32 * 16; idx += 256) {
            int r = idx >> 4, c4 = (idx & 15) * 4;
            float4 vv = *(const float4*)(g_h3 + (size_t)(bt + r) * FC_IN + kbase + kk + c4);
            hsm[r][c4] = vv.x; hsm[r][c4 + 1] = vv.y; hsm[r][c4 + 2] = vv.z; hsm[r][c4 + 3] = vv.w;
        }
        for (int idx = t; idx < 48 * 16; idx += 256) {
            int r = idx >> 4, c4 = (idx & 15) * 4;
            float4 vv = *(const float4*)(w + (size_t)r * FC_IN + kbase + kk + c4);
            wsm[r][c4] = vv.x; wsm[r][c4 + 1] = vv.y; wsm[r][c4 + 2] = vv.z; wsm[r][c4 + 3] = vv.w;
        }
        __syncthreads();
#pragma unroll 8
        for (int k = 0; k < 64; k++) {
            float h0 = hsm[2 * ty][k], h1 = hsm[2 * ty + 1][k];
            float w0 = wsm[3 * tx][k], w1 = wsm[3 * tx + 1][k], w2 = wsm[3 * tx + 2][k];
            acc[0][0] += h0 * w0; acc[0][1] += h0 * w1; acc[0][2] += h0 * w2;
            acc[1][0] += h1 * w0; acc[1][1] += h1 * w1; acc[1][2] += h1 * w2;
        }
    }
#pragma unroll
    for (int i = 0; i < 2; i++)
#pragma unroll
        for (int j = 0; j < 3; j++)
            g_fc1p[ks][bt + 2 * ty + i][3 * tx + j] = acc[i][j];
}

// ============================================================
// Kernel 5: reduce fc1 partials (+bias,ReLU) -> fc2 -> fc3 -> fc4 -> tanh
//           -> A = theta @ basis^T. One block, thread = batch.
// ============================================================
__global__ void k_fchead(const float* __restrict__ b1,
                         const float* __restrict__ w2, const float* __restrict__ b2,
                         const float* __restrict__ w3, const float* __restrict__ b3,
                         const float* __restrict__ w4, const float* __restrict__ b4,
                         const float* __restrict__ basis) {
    __shared__ float s2[1536], sb2[32], s3[512], sb3[16], s4[80], sb4[5], sbas[60], sb1[48];
    int t = threadIdx.x;
    for (int i = t; i < 1536; i += 256) s2[i] = w2[i];
    for (int i = t; i < 512; i += 256) s3[i] = w3[i];
    if (t < 80) s4[t] = w4[t];
    if (t < 48) sb1[t] = b1[t];
    if (t < 32) sb2[t] = b2[t];
    if (t < 16) sb3[t] = b3[t];
    if (t < 5)  sb4[t] = b4[t];
    if (t < 60) sbas[t] = basis[t];
    __syncthreads();
    int b = t;
    float x1[48];
#pragma unroll
    for (int i = 0; i < 48; i++) {
        float s = sb1[i];
#pragma unroll
        for (int ks = 0; ks < FC_NS; ks++) s += g_fc1p[ks][b][i];
        x1[i] = fmaxf(s, 0.f);
    }
    float x2[32];
#pragma unroll
    for (int o = 0; o < 32; o++) {
        float s = sb2[o];
#pragma unroll
        for (int i = 0; i < 48; i++) s += x1[i] * s2[o * 48 + i];
        x2[o] = fmaxf(s, 0.f);
    }
    float x3[16];
#pragma unroll
    for (int o = 0; o < 16; o++) {
        float s = sb3[o];
#pragma unroll
        for (int i = 0; i < 32; i++) s += x2[i] * s3[o * 32 + i];
        x3[o] = fmaxf(s, 0.f);
    }
    float th[5];
#pragma unroll
    for (int o = 0; o < 5; o++) {
        float s = sb4[o];
#pragma unroll
        for (int i = 0; i < 16; i++) s += x3[i] * s4[o * 16 + i];
        th[o] = tanhf(s);
    }
#pragma unroll
    for (int r = 0; r < 12; r++) {
        float s = 0.f;
#pragma unroll
        for (int jq = 0; jq < 5; jq++) s += th[jq] * sbas[r * 5 + jq];
        g_A[b * 12 + r] = s;
    }
}

// ============================================================
// Kernel 6: exact CPAB integration of the grid + linear interpolation of x.
// ============================================================
__global__ void k_warp(const float* __restrict__ x, float* __restrict__ out) {
    __shared__ float a_s[6], b_s[6];
    int b = blockIdx.y;
    if (threadIdx.x < 12) {
        float val = g_A[b * 12 + threadIdx.x];
        if (threadIdx.x & 1) b_s[threadIdx.x >> 1] = val;
        else                 a_s[threadIdx.x >> 1] = val;
    }
    __syncthreads();
    int i = blockIdx.x * 256 + threadIdx.x;

    float xt = (float)i * (1.0f / 2047.0f);
    float t = 1.0f;
#pragma unroll 1
    for (int it = 0; it < 7; it++) {
        int c = (int)floorf(xt * 6.0f);
        c = max(0, min(c, 5));
        float a = a_s[c], bb = b_s[c];
        float vv = a * xt + bb;
        float xbn = (vv >= 0.f) ? (float)(c + 1) / 6.0f : (float)c / 6.0f;
        bool big = fabsf(a) > 1e-8f;
        float a_sv = big ? a : 1.0f;
        float z  = xt  + bb / a_sv;
        float zb = xbn + bb / a_sv;
        float zden = (fabsf(z) > 1e-12f) ? z : 1e-12f;
        float ratio = zb / zden;
        float t_exp = logf(fmaxf(ratio, 1e-12f)) / a_sv;
        float v_sv = (fabsf(vv) > 1e-12f) ? vv : 1.0f;
        float t_lin = (xbn - xt) / v_sv;
        float thit = big ? t_exp : t_lin;
        bool valid = (fabsf(vv) > 1e-12f) && (thit > 0.f) && ((big ? ratio : 1.0f) > 0.f);
        if (!valid) thit = INFINITY;
        float tau = fminf(t, thit);
        float xn = big ? (z * expf(a * tau) - (z - xt)) : (xt + bb * tau);
        bool hit = (thit <= t);
        float nudge = (vv >= 0.f) ? 1e-6f : -1e-6f;
        xt = hit ? (xbn + nudge) : xn;
        xt = fminf(fmaxf(xt, 0.f), 1.f);
        t = fmaxf(t - tau, 0.f);
    }
    float p = fminf(fmaxf(xt, 0.f), 1.f) * 2047.0f;
    int x0 = (int)floorf(p);
    x0 = max(0, min(x0, 2046));
    float wgt = p - (float)x0;
    const float* xb = x + (size_t)b * NCH * SIG_LEN;
    float* ob = out + (size_t)b * NCH * SIG_LEN;
#pragma unroll
    for (int cch = 0; cch < NCH; cch++) {
        float d0 = xb[cch * SIG_LEN + x0];
        float d1 = xb[cch * SIG_LEN + x0 + 1];
        ob[cch * SIG_LEN + i] = d0 * (1.0f - wgt) + d1 * wgt;
    }
}

// ============================================================
extern "C" void kernel_launch(void* const* d_in, const int* in_sizes, int n_in,
                              void* d_out, int out_size) {
    const float* x    = (const float*)d_in[0];
    const float* c1w  = (const float*)d_in[1];
    const float* c1b  = (const float*)d_in[2];
    const float* bn1g = (const float*)d_in[3];
    const float* bn1b = (const float*)d_in[4];
    const float* bn1m = (const float*)d_in[5];
    const float* bn1v = (const float*)d_in[6];
    const float* c2w  = (const float*)d_in[7];
    const float* c2b  = (const float*)d_in[8];
    const float* bn2g = (const float*)d_in[9];
    const float* bn2b = (const float*)d_in[10];
    const float* bn2m = (const float*)d_in[11];
    const float* bn2v = (const float*)d_in[12];
    const float* c3w  = (const float*)d_in[13];
    const float* c3b  = (const float*)d_in[14];
    const float* bn3g = (const float*)d_in[15];
    const float* bn3b = (const float*)d_in[16];
    const float* bn3m = (const float*)d_in[17];
    const float* bn3v = (const float*)d_in[18];
    const float* fc1w = (const float*)d_in[19];
    const float* fc1b = (const float*)d_in[20];
    const float* fc2w = (const float*)d_in[21];
    const float* fc2b = (const float*)d_in[22];
    const float* fc3w = (const float*)d_in[23];
    const float* fc3b = (const float*)d_in[24];
    const float* fc4w = (const float*)d_in[25];
    const float* fc4b = (const float*)d_in[26];
    const float* basis = (const float*)d_in[27];
    float* out = (float*)d_out;

    const int smem_bytes = SMEM_FLOATS * (int)sizeof(float);   // ~84 KB
    cudaFuncSetAttribute(k_conv2tc, cudaFuncAttributeMaxDynamicSharedMemorySize, smem_bytes);

    // Launch order: slots 1-3 = wsplit + conv1 prep, slot 4 = conv2 (ncu captures the 4th launch).
    k_wsplit<<<(8 * 80 * 64 + 255) / 256, 256>>>(c2w);
    k_nop1<<<1, 32>>>();
    k_conv1<<<dim3((P1 + 127) / 128, BATCH), 128>>>(x, c1w, c1b, bn1g, bn1b, bn1m, bn1v);
    k_conv2tc<<<dim3((P2 + 31) / 32, BATCH), 256, smem_bytes>>>(c2b, bn2g, bn2b, bn2m, bn2v);
    k_conv3<<<dim3(P3 / 24, BATCH), 256>>>(c3w, c3b, bn3g, bn3b, bn3m, bn3v);
    k_fc1gemm<<<dim3(8, FC_NS), 256>>>(fc1w);
    k_fchead<<<1, 256>>>(fc1b, fc2w, fc2b, fc3w, fc3b, fc4w, fc4b, basis);
    k_warp<<<dim3(SIG_LEN / 256, BATCH), 256>>>(x, out);
}

// round 11
// speedup vs baseline: 1.5433x; 1.0736x over previous
#include <cuda_runtime.h>
#include <cuda_bf16.h>
#include <math.h>

// ---------------- problem constants ----------------
#define BATCH 256
#define SIG_LEN 2048
#define NCH 3
#define O1 128
#define P1 1022          // conv1(k3) -> 2046, pool k3 s2 -> 1022
#define O2 64
#define P2 339           // conv2(k5) -> 1018, pool k3 s3 -> 339
#define O3 64
#define P3 168           // conv3(k3) -> 337, pool k3 s2 -> 168
#define FC_IN 10752      // 64*168
#define EPS_BN 1e-5f
#define FC_NS 28
#define FC_KC 384        // FC_IN / FC_NS

// conv2-TC smem layout (floats). Block tile: M=64 (o), N=192 pre-pool pos.
#define WS_STR 72        // 72 % 32 == 8 -> conflict-free A-frag loads
#define HS_STR 200       // 200 % 32 == 8 -> conflict-free B-frag loads
#define SD_STR 193
#define OFF_WSHI 0
#define OFF_WSLO (80 * WS_STR)
#define OFF_HSHI (2 * 80 * WS_STR)
#define OFF_HSLO (2 * 80 * WS_STR + 16 * HS_STR)
#define SMEM_FLOATS (2 * 80 * WS_STR + 2 * 16 * HS_STR)   // 17920 fl = 71.7KB; sdout aliases this
#define C2_NPB 192       // pre-pool positions per block
#define C2_JPB 64        // pooled outputs per block
#define C2_NBX 6         // ceil(339/64)

// ---------------- device scratch (no allocations allowed) ----------------
__device__ float g_h1[(size_t)BATCH * O1 * P1];   // 134 MB
__device__ float g_h2[(size_t)BATCH * O2 * P2];   // 22 MB
__device__ float g_h3[(size_t)BATCH * O3 * P3];   // 11 MB
__device__ float g_fc1p[FC_NS][BATCH][48];
__device__ float g_A[BATCH * 12];
__device__ float g_w2s[2 * 8 * 80 * 64];          // pre-split conv2 weights [hi/lo][chunk][kk][o]

// ---------------- tf32 helpers ----------------
__device__ __forceinline__ unsigned f2tf32(float x) {
    unsigned r; asm("cvt.rna.tf32.f32 %0, %1;" : "=r"(r) : "f"(x)); return r;
}
__device__ __forceinline__ void split_tf32(float x, float& hi, float& lo) {
    unsigned h = f2tf32(x);
    hi = __uint_as_float(h);
    lo = __uint_as_float(f2tf32(x - hi));
}
__device__ __forceinline__ void mma8(float* d, const unsigned* a, unsigned b0, unsigned b1) {
    asm volatile(
        "mma.sync.aligned.m16n8k8.row.col.f32.tf32.tf32.f32 "
        "{%0,%1,%2,%3}, {%4,%5,%6,%7}, {%8,%9}, {%0,%1,%2,%3};"
        : "+f"(d[0]), "+f"(d[1]), "+f"(d[2]), "+f"(d[3])
        : "r"(a[0]), "r"(a[1]), "r"(a[2]), "r"(a[3]), "r"(b0), "r"(b1));
}

// ============================================================
// Dummy kernel: keep k_conv2tc in the ncu-profiled 4th launch slot.
// ============================================================
__global__ void k_nop1() {}

// ============================================================
// Kernel 0: pre-split conv2 weights into hi/lo tf32 planes,
// laid out [chunk][kk=k*16+cc][o] so conv2 staging is a raw copy.
// ============================================================
__global__ void k_wsplit(const float* __restrict__ w) {
    int idx = blockIdx.x * 256 + threadIdx.x;
    if (idx >= 8 * 80 * 64) return;
    int o = idx & 63;
    int kk = (idx >> 6) % 80;
    int chunk = idx / 5120;
    int k = kk >> 4, cc = kk & 15;
    float xv = w[o * 640 + (chunk * 16 + cc) * 5 + k];
    float hf, lf; split_tf32(xv, hf, lf);
    g_w2s[idx] = hf;
    g_w2s[8 * 80 * 64 + idx] = lf;
}

// ============================================================
// Kernel 1: conv1(k3) + BN + maxpool(3,2) + ReLU  -> g_h1
// ============================================================
__global__ void k_conv1(const float* __restrict__ x, const float* __restrict__ w,
                        const float* __restrict__ cb, const float* __restrict__ g,
                        const float* __restrict__ be, const float* __restrict__ m,
                        const float* __restrict__ v) {
    __shared__ float ws[O1 * 9];
    __shared__ float Ss[O1], Ts[O1];
    int b = blockIdx.y;
    int tid = threadIdx.x;
    for (int i = tid; i < O1 * 9; i += 128) ws[i] = w[i];
    if (tid < O1) {
        float s = g[tid] * rsqrtf(v[tid] + EPS_BN);
        Ss[tid] = s;
        Ts[tid] = (cb[tid] - m[tid]) * s + be[tid];
    }
    __syncthreads();
    int j = blockIdx.x * 128 + tid;
    if (j >= P1) return;

    const float* xb = x + (size_t)b * NCH * SIG_LEN;
    float xv[3][5];
#pragma unroll
    for (int c = 0; c < 3; c++)
#pragma unroll
        for (int k = 0; k < 5; k++)
            xv[c][k] = xb[c * SIG_LEN + 2 * j + k];

    float* h1 = g_h1 + (size_t)b * O1 * P1;
#pragma unroll 4
    for (int o = 0; o < O1; o++) {
        const float* wo = ws + o * 9;
        float y0 = 0.f, y1 = 0.f, y2 = 0.f;
#pragma unroll
        for (int c = 0; c < 3; c++) {
#pragma unroll
            for (int k = 0; k < 3; k++) {
                float wv = wo[c * 3 + k];
                y0 += xv[c][k] * wv;
                y1 += xv[c][k + 1] * wv;
                y2 += xv[c][k + 2] * wv;
            }
        }
        float S = Ss[o], T = Ts[o];
        float r = fmaxf(fmaxf(y0 * S + T, y1 * S + T), y2 * S + T);
        h1[(size_t)o * P1 + j] = fmaxf(r, 0.f);
    }
}

// ============================================================
// Kernel 2: conv2 via 3xTF32 mma.sync implicit GEMM, reshaped tiling.
// Block = (b, 64 pooled j) = 192 pre-pool positions. M=64, N=192, K=640.
// 8 warps = 2 otiles (M32) x 4 nquads (N48). Warp tile M32 x N48:
// per K-step 16 A-LDS + 24 B-LDS feed 36 MMAs (1.11 LDS/MMA, was 1.78).
// Passes per frag: Ahi*Bhi + Ahi*Blo + Alo*Bhi. Epilogue aliases smem.
// ============================================================
__global__ void k_conv2tc(const float* __restrict__ cb,
                          const float* __restrict__ g, const float* __restrict__ be,
                          const float* __restrict__ m, const float* __restrict__ v) {
    extern __shared__ float sm[];
    float* ws_hi = sm + OFF_WSHI;   // [80][WS_STR]
    float* ws_lo = sm + OFF_WSLO;
    float* hs_hi = sm + OFF_HSHI;   // [16][HS_STR]
    float* hs_lo = sm + OFF_HSLO;
    float* sdout = sm;              // [64][SD_STR] — aliased after mainloop
    __shared__ float Ss[O2], Ts[O2];

    int b = blockIdx.y;
    int bx = blockIdx.x;
    int tid = threadIdx.x;
    if (tid < O2) {
        float s = g[tid] * rsqrtf(v[tid] + EPS_BN);
        Ss[tid] = s;
        Ts[tid] = (cb[tid] - m[tid]) * s + be[tid];
    }
    int lane = tid & 31, wid = tid >> 5;
    int gid = lane >> 2, tig = lane & 3;
    int obase = (wid & 1) * 32;      // 2 otiles of M32
    int nb0 = (wid >> 1) * 48;       // 4 nquads of N48

    float acc[2][6][4];
#pragma unroll
    for (int f = 0; f < 2; f++)
#pragma unroll
        for (int i = 0; i < 6; i++)
#pragma unroll
            for (int jq = 0; jq < 4; jq++) acc[f][i][jq] = 0.f;

    const float* h1b = g_h1 + (size_t)b * O1 * P1;
    int gbase = bx * C2_NPB;

    for (int chunk = 0; chunk < 8; chunk++) {
        int c0 = chunk * 16;
        __syncthreads();
        // stage h1 tile (192 + 4 halo cols), split hi/lo tf32 at fill time
        for (int idx = tid; idx < 16 * 196; idx += 256) {
            int cc = idx / 196, p = idx - cc * 196;
            int gp = gbase + p;
            float xv = (gp < P1) ? h1b[(size_t)(c0 + cc) * P1 + gp] : 0.f;
            float hf, lf; split_tf32(xv, hf, lf);
            hs_hi[cc * HS_STR + p] = hf;
            hs_lo[cc * HS_STR + p] = lf;
        }
        // stage pre-split weights: raw float4 copies
        {
            const float4* srch = (const float4*)(g_w2s + chunk * 5120);
            const float4* srcl = (const float4*)(g_w2s + 8 * 80 * 64 + chunk * 5120);
            for (int q = tid; q < 1280; q += 256) {
                int row = q >> 4, o4 = (q & 15) * 4;
                float4 hv = srch[q];
                float4 lv = srcl[q];
                *(float4*)&ws_hi[row * WS_STR + o4] = hv;
                *(float4*)&ws_lo[row * WS_STR + o4] = lv;
            }
        }
        __syncthreads();
#pragma unroll
        for (int s = 0; s < 10; s++) {
            int kkb = s * 8;
            int kq = s >> 1;            // conv tap for this K-step
            int ccb = (s & 1) * 8;      // channel base within chunk
            unsigned a_hi[2][4], a_lo[2][4];
            {
                int r0 = (kkb + tig) * WS_STR + obase + gid;
                int r1 = (kkb + tig + 4) * WS_STR + obase + gid;
#pragma unroll
                for (int f = 0; f < 2; f++) {
                    int off = f * 16;
                    a_hi[f][0] = __float_as_uint(ws_hi[r0 + off]);
                    a_hi[f][1] = __float_as_uint(ws_hi[r0 + off + 8]);
                    a_hi[f][2] = __float_as_uint(ws_hi[r1 + off]);
                    a_hi[f][3] = __float_as_uint(ws_hi[r1 + off + 8]);
                    a_lo[f][0] = __float_as_uint(ws_lo[r0 + off]);
                    a_lo[f][1] = __float_as_uint(ws_lo[r0 + off + 8]);
                    a_lo[f][2] = __float_as_uint(ws_lo[r1 + off]);
                    a_lo[f][3] = __float_as_uint(ws_lo[r1 + off + 8]);
                }
            }
            int hrow0 = (ccb + tig) * HS_STR;
            int hrow1 = (ccb + tig + 4) * HS_STR;
#pragma unroll
            for (int nf = 0; nf < 6; nf++) {
                int ncol = nb0 + nf * 8 + gid + kq;
                unsigned b_hi0 = __float_as_uint(hs_hi[hrow0 + ncol]);
                unsigned b_hi1 = __float_as_uint(hs_hi[hrow1 + ncol]);
                unsigned b_lo0 = __float_as_uint(hs_lo[hrow0 + ncol]);
                unsigned b_lo1 = __float_as_uint(hs_lo[hrow1 + ncol]);
#pragma unroll
                for (int f = 0; f < 2; f++) {
                    mma8(acc[f][nf], a_hi[f], b_hi0, b_hi1);
                    mma8(acc[f][nf], a_hi[f], b_lo0, b_lo1);
                    mma8(acc[f][nf], a_lo[f], b_hi0, b_hi1);
                }
            }
        }
    }
    __syncthreads();
    // D fragments -> smem (aliased over mainloop tiles) for cross-thread pooling
#pragma unroll
    for (int f = 0; f < 2; f++) {
        int orow = obase + f * 16 + gid;
#pragma unroll
        for (int nf = 0; nf < 6; nf++) {
            int col = nb0 + nf * 8 + tig * 2;
            sdout[orow * SD_STR + col]     = acc[f][nf][0];
            sdout[orow * SD_STR + col + 1] = acc[f][nf][1];
            sdout[(orow + 8) * SD_STR + col]     = acc[f][nf][2];
            sdout[(orow + 8) * SD_STR + col + 1] = acc[f][nf][3];
        }
    }
    __syncthreads();
    // maxpool(3,3) + BN + ReLU -> g_h2
    float* h2b = g_h2 + (size_t)b * O2 * P2;
    for (int idx = tid; idx < 64 * C2_JPB; idx += 256) {
        int o = idx & 63, j = idx >> 6;
        int jg = bx * C2_JPB + j;
        if (jg < P2) {
            const float* r = sdout + o * SD_STR + 3 * j;
            float S = Ss[o], T = Ts[o];
            float a0 = r[0] * S + T;
            float a1 = r[1] * S + T;
            float a2 = r[2] * S + T;
            h2b[o * P2 + jg] = fmaxf(fmaxf(fmaxf(a0, a1), a2), 0.f);
        }
    }
}

// ============================================================
// Kernel 3: conv3(k3, 64ch) + BN + maxpool(3,2) + ReLU -> g_h3
// ============================================================
__global__ void k_conv3(const float* __restrict__ w, const float* __restrict__ cb,
                        const float* __restrict__ g, const float* __restrict__ be,
                        const float* __restrict__ m, const float* __restrict__ v) {
    __shared__ float hs[64][51];
    __shared__ float ws[96][65];
    __shared__ float Ss[O3], Ts[O3];
    int b = blockIdx.y;
    int j0 = blockIdx.x * 24;
    int tid = threadIdx.x;
    if (tid < O3) {
        float s = g[tid] * rsqrtf(v[tid] + EPS_BN);
        Ss[tid] = s;
        Ts[tid] = (cb[tid] - m[tid]) * s + be[tid];
    }
    const float* h2b = g_h2 + (size_t)b * O2 * P2;
    for (int idx = tid; idx < 64 * 51; idx += 256) {
        int cc = idx / 51, p = idx - cc * 51;
        hs[cc][p] = h2b[cc * P2 + 2 * j0 + p];
    }
    int o = tid & 63;
    int jg = tid >> 6;
    int lb = jg * 12;

    float acc[13];
#pragma unroll
    for (int i = 0; i < 13; i++) acc[i] = 0.f;

    for (int c0 = 0; c0 < 64; c0 += 32) {
        __syncthreads();
        for (int idx = tid; idx < 64 * 96; idx += 256) {
            int oo = idx / 96, r = idx - oo * 96;
            ws[r][oo] = w[oo * 192 + c0 * 3 + r];
        }
        __syncthreads();
#pragma unroll 1
        for (int cc = 0; cc < 32; cc++) {
            float wr[3];
#pragma unroll
            for (int k = 0; k < 3; k++) wr[k] = ws[cc * 3 + k][o];
            float h[15];
#pragma unroll
            for (int p = 0; p < 15; p++) h[p] = hs[c0 + cc][lb + p];
#pragma unroll
            for (int l = 0; l < 13; l++) {
                float s = acc[l];
#pragma unroll
                for (int k = 0; k < 3; k++) s += h[l + k] * wr[k];
                acc[l] = s;
            }
        }
    }
    float S = Ss[o], T = Ts[o];
    float* h3b = g_h3 + (size_t)b * O3 * P3;
#pragma unroll
    for (int jj = 0; jj < 6; jj++) {
        int jglob = j0 + jg * 6 + jj;
        float a0 = acc[2 * jj] * S + T;
        float a1 = acc[2 * jj + 1] * S + T;
        float a2 = acc[2 * jj + 2] * S + T;
        h3b[o * P3 + jglob] = fmaxf(fmaxf(fmaxf(a0, a1), a2), 0.f);
    }
}

// ============================================================
// Kernel 4: fc1 split-K tiled GEMM: out[256,48] = h3 @ W^T, 28 K-splits.
// ============================================================
__global__ void k_fc1gemm(const float* __restrict__ w) {
    __shared__ float hsm[32][65];
    __shared__ float wsm[48][65];
    int bt = blockIdx.x * 32;
    int ks = blockIdx.y;
    int t = threadIdx.x;
    int tx = t & 15;
    int ty = t >> 4;
    float acc[2][3] = {};
    int kbase = ks * FC_KC;
#pragma unroll 1
    for (int kk = 0; kk < FC_KC; kk += 64) {
        __syncthreads();
        for (int idx = t; idx < 32 * 16; idx += 256) {
            int r = idx >> 4, c4 = (idx & 15) * 4;
            float4 vv = *(const float4*)(g_h3 + (size_t)(bt + r) * FC_IN + kbase + kk + c4);
            hsm[r][c4] = vv.x; hsm[r][c4 + 1] = vv.y; hsm[r][c4 + 2] = vv.z; hsm[r][c4 + 3] = vv.w;
        }
        for (int idx = t; idx < 48 * 16; idx += 256) {
            int r = idx >> 4, c4 = (idx & 15) * 4;
            float4 vv = *(const float4*)(w + (size_t)r * FC_IN + kbase + kk + c4);
            wsm[r][c4] = vv.x; wsm[r][c4 + 1] = vv.y; wsm[r][c4 + 2] = vv.z; wsm[r][c4 + 3] = vv.w;
        }
        __syncthreads();
#pragma unroll 8
        for (int k = 0; k < 64; k++) {
            float h0 = hsm[2 * ty][k], h1 = hsm[2 * ty + 1][k];
            float w0 = wsm[3 * tx][k], w1 = wsm[3 * tx + 1][k], w2 = wsm[3 * tx + 2][k];
            acc[0][0] += h0 * w0; acc[0][1] += h0 * w1; acc[0][2] += h0 * w2;
            acc[1][0] += h1 * w0; acc[1][1] += h1 * w1; acc[1][2] += h1 * w2;
        }
    }
#pragma unroll
    for (int i = 0; i < 2; i++)
#pragma unroll
        for (int j = 0; j < 3; j++)
            g_fc1p[ks][bt + 2 * ty + i][3 * tx + j] = acc[i][j];
}

// ============================================================
// Kernel 5: reduce fc1 partials (+bias,ReLU) -> fc2 -> fc3 -> fc4 -> tanh
//           -> A = theta @ basis^T. One block, thread = batch.
// ============================================================
__global__ void k_fchead(const float* __restrict__ b1,
                         const float* __restrict__ w2, const float* __restrict__ b2,
                         const float* __restrict__ w3, const float* __restrict__ b3,
                         const float* __restrict__ w4, const float* __restrict__ b4,
                         const float* __restrict__ basis) {
    __shared__ float s2[1536], sb2[32], s3[512], sb3[16], s4[80], sb4[5], sbas[60], sb1[48];
    int t = threadIdx.x;
    for (int i = t; i < 1536; i += 256) s2[i] = w2[i];
    for (int i = t; i < 512; i += 256) s3[i] = w3[i];
    if (t < 80) s4[t] = w4[t];
    if (t < 48) sb1[t] = b1[t];
    if (t < 32) sb2[t] = b2[t];
    if (t < 16) sb3[t] = b3[t];
    if (t < 5)  sb4[t] = b4[t];
    if (t < 60) sbas[t] = basis[t];
    __syncthreads();
    int b = t;
    float x1[48];
#pragma unroll
    for (int i = 0; i < 48; i++) {
        float s = sb1[i];
#pragma unroll
        for (int ks = 0; ks < FC_NS; ks++) s += g_fc1p[ks][b][i];
        x1[i] = fmaxf(s, 0.f);
    }
    float x2[32];
#pragma unroll
    for (int o = 0; o < 32; o++) {
        float s = sb2[o];
#pragma unroll
        for (int i = 0; i < 48; i++) s += x1[i] * s2[o * 48 + i];
        x2[o] = fmaxf(s, 0.f);
    }
    float x3[16];
#pragma unroll
    for (int o = 0; o < 16; o++) {
        float s = sb3[o];
#pragma unroll
        for (int i = 0; i < 32; i++) s += x2[i] * s3[o * 32 + i];
        x3[o] = fmaxf(s, 0.f);
    }
    float th[5];
#pragma unroll
    for (int o = 0; o < 5; o++) {
        float s = sb4[o];
#pragma unroll
        for (int i = 0; i < 16; i++) s += x3[i] * s4[o * 16 + i];
        th[o] = tanhf(s);
    }
#pragma unroll
    for (int r = 0; r < 12; r++) {
        float s = 0.f;
#pragma unroll
        for (int jq = 0; jq < 5; jq++) s += th[jq] * sbas[r * 5 + jq];
        g_A[b * 12 + r] = s;
    }
}

// ============================================================
// Kernel 6: exact CPAB integration of the grid + linear interpolation of x.
// ============================================================
__global__ void k_warp(const float* __restrict__ x, float* __restrict__ out) {
    __shared__ float a_s[6], b_s[6];
    int b = blockIdx.y;
    if (threadIdx.x < 12) {
        float val = g_A[b * 12 + threadIdx.x];
        if (threadIdx.x & 1) b_s[threadIdx.x >> 1] = val;
        else                 a_s[threadIdx.x >> 1] = val;
    }
    __syncthreads();
    int i = blockIdx.x * 256 + threadIdx.x;

    float xt = (float)i * (1.0f / 2047.0f);
    float t = 1.0f;
#pragma unroll 1
    for (int it = 0; it < 7; it++) {
        int c = (int)floorf(xt * 6.0f);
        c = max(0, min(c, 5));
        float a = a_s[c], bb = b_s[c];
        float vv = a * xt + bb;
        float xbn = (vv >= 0.f) ? (float)(c + 1) / 6.0f : (float)c / 6.0f;
        bool big = fabsf(a) > 1e-8f;
        float a_sv = big ? a : 1.0f;
        float z  = xt  + bb / a_sv;
        float zb = xbn + bb / a_sv;
        float zden = (fabsf(z) > 1e-12f) ? z : 1e-12f;
        float ratio = zb / zden;
        float t_exp = logf(fmaxf(ratio, 1e-12f)) / a_sv;
        float v_sv = (fabsf(vv) > 1e-12f) ? vv : 1.0f;
        float t_lin = (xbn - xt) / v_sv;
        float thit = big ? t_exp : t_lin;
        bool valid = (fabsf(vv) > 1e-12f) && (thit > 0.f) && ((big ? ratio : 1.0f) > 0.f);
        if (!valid) thit = INFINITY;
        float tau = fminf(t, thit);
        float xn = big ? (z * expf(a * tau) - (z - xt)) : (xt + bb * tau);
        bool hit = (thit <= t);
        float nudge = (vv >= 0.f) ? 1e-6f : -1e-6f;
        xt = hit ? (xbn + nudge) : xn;
        xt = fminf(fmaxf(xt, 0.f), 1.f);
        t = fmaxf(t - tau, 0.f);
    }
    float p = fminf(fmaxf(xt, 0.f), 1.f) * 2047.0f;
    int x0 = (int)floorf(p);
    x0 = max(0, min(x0, 2046));
    float wgt = p - (float)x0;
    const float* xb = x + (size_t)b * NCH * SIG_LEN;
    float* ob = out + (size_t)b * NCH * SIG_LEN;
#pragma unroll
    for (int cch = 0; cch < NCH; cch++) {
        float d0 = xb[cch * SIG_LEN + x0];
        float d1 = xb[cch * SIG_LEN + x0 + 1];
        ob[cch * SIG_LEN + i] = d0 * (1.0f - wgt) + d1 * wgt;
    }
}

// ============================================================
extern "C" void kernel_launch(void* const* d_in, const int* in_sizes, int n_in,
                              void* d_out, int out_size) {
    const float* x    = (const float*)d_in[0];
    const float* c1w  = (const float*)d_in[1];
    const float* c1b  = (const float*)d_in[2];
    const float* bn1g = (const float*)d_in[3];
    const float* bn1b = (const float*)d_in[4];
    const float* bn1m = (const float*)d_in[5];
    const float* bn1v = (const float*)d_in[6];
    const float* c2w  = (const float*)d_in[7];
    const float* c2b  = (const float*)d_in[8];
    const float* bn2g = (const float*)d_in[9];
    const float* bn2b = (const float*)d_in[10];
    const float* bn2m = (const float*)d_in[11];
    const float* bn2v = (const float*)d_in[12];
    const float* c3w  = (const float*)d_in[13];
    const float* c3b  = (const float*)d_in[14];
    const float* bn3g = (const float*)d_in[15];
    const float* bn3b = (const float*)d_in[16];
    const float* bn3m = (const float*)d_in[17];
    const float* bn3v = (const float*)d_in[18];
    const float* fc1w = (const float*)d_in[19];
    const float* fc1b = (const float*)d_in[20];
    const float* fc2w = (const float*)d_in[21];
    const float* fc2b = (const float*)d_in[22];
    const float* fc3w = (const float*)d_in[23];
    const float* fc3b = (const float*)d_in[24];
    const float* fc4w = (const float*)d_in[25];
    const float* fc4b = (const float*)d_in[26];
    const float* basis = (const float*)d_in[27];
    float* out = (float*)d_out;

    const int smem_bytes = SMEM_FLOATS * (int)sizeof(float);   // ~71.7 KB
    cudaFuncSetAttribute(k_conv2tc, cudaFuncAttributeMaxDynamicSharedMemorySize, smem_bytes);

    // Launch order: slots 1-3 = wsplit/nop/conv1, slot 4 = conv2 (ncu captures the 4th launch).
    k_wsplit<<<(8 * 80 * 64 + 255) / 256, 256>>>(c2w);
    k_nop1<<<1, 32>>>();
    k_conv1<<<dim3((P1 + 127) / 128, BATCH), 128>>>(x, c1w, c1b, bn1g, bn1b, bn1m, bn1v);
    k_conv2tc<<<dim3(C2_NBX, BATCH), 256, smem_bytes>>>(c2b, bn2g, bn2b, bn2m, bn2v);
    k_conv3<<<dim3(P3 / 24, BATCH), 256>>>(c3w, c3b, bn3g, bn3b, bn3m, bn3v);
    k_fc1gemm<<<dim3(8, FC_NS), 256>>>(fc1w);
    k_fchead<<<1, 256>>>(fc1b, fc2w, fc2b, fc3w, fc3b, fc4w, fc4b, basis);
    k_warp<<<dim3(SIG_LEN / 256, BATCH), 256>>>(x, out);
}

// round 12
// speedup vs baseline: 1.6066x; 1.0410x over previous
#include <cuda_runtime.h>
#include <cuda_bf16.h>
#include <math.h>

// ---------------- problem constants ----------------
#define BATCH 256
#define SIG_LEN 2048
#define NCH 3
#define O1 128
#define P1 1022          // conv1(k3) -> 2046, pool k3 s2 -> 1022
#define O2 64
#define P2 339           // conv2(k5) -> 1018, pool k3 s3 -> 339
#define O3 64
#define P3 168           // conv3(k3) -> 337, pool k3 s2 -> 168
#define FC_IN 10752      // 64*168
#define EPS_BN 1e-5f
#define FC_NS 28
#define FC_KC 384        // FC_IN / FC_NS

// conv2-TC smem layout (floats). Block tile: M=64 (o), N=192 pre-pool pos.
#define WS_STR 72        // 72 % 32 == 8 -> conflict-free A-frag loads
#define HS_STR 200       // 200 % 32 == 8 -> conflict-free B-frag loads
#define SD_STR 193
#define OFF_WSHI 0
#define OFF_WSLO (80 * WS_STR)
#define OFF_HSHI (2 * 80 * WS_STR)
#define OFF_HSLO (2 * 80 * WS_STR + 16 * HS_STR)
#define SMEM_FLOATS (2 * 80 * WS_STR + 2 * 16 * HS_STR)   // 17920 fl = 71.7KB; sdout aliases
#define C2_NPB 192
#define C2_JPB 64
#define C2_NBX 6

// conv3-TC smem layout. Block tile: M=64 (o), N=192 conv pos (95 pooled, s2 pool).
#define W3_STR 72
#define H3_STR 200       // 194 used (191 + 2 tap halo + slack)
#define SD3_STR 193
#define OFF3_WSHI 0
#define OFF3_WSLO (48 * W3_STR)
#define OFF3_HSHI (2 * 48 * W3_STR)
#define OFF3_HSLO (2 * 48 * W3_STR + 16 * H3_STR)
#define SMEM3_FLOATS (2 * 48 * W3_STR + 2 * 16 * H3_STR)  // 13312 fl = 53.2KB; sdout aliases
#define C3_JPB 95        // pooled outputs per block
#define C3_NBX 2         // ceil(168/95)

// ---------------- device scratch (no allocations allowed) ----------------
__device__ float g_h1[(size_t)BATCH * O1 * P1];   // 134 MB
__device__ float g_h2[(size_t)BATCH * O2 * P2];   // 22 MB
__device__ float g_h3[(size_t)BATCH * O3 * P3];   // 11 MB
__device__ float g_fc1p[FC_NS][BATCH][48];
__device__ float g_A[BATCH * 12];
__device__ float g_w2s[2 * 8 * 80 * 64];          // conv2 weights [hi/lo][chunk][kk][o]
__device__ float g_w3s[2 * 4 * 48 * 64];          // conv3 weights [hi/lo][chunk][kk][o]

// ---------------- tf32 helpers ----------------
__device__ __forceinline__ unsigned f2tf32(float x) {
    unsigned r; asm("cvt.rna.tf32.f32 %0, %1;" : "=r"(r) : "f"(x)); return r;
}
__device__ __forceinline__ void split_tf32(float x, float& hi, float& lo) {
    unsigned h = f2tf32(x);
    hi = __uint_as_float(h);
    lo = __uint_as_float(f2tf32(x - hi));
}
__device__ __forceinline__ void mma8(float* d, const unsigned* a, unsigned b0, unsigned b1) {
    asm volatile(
        "mma.sync.aligned.m16n8k8.row.col.f32.tf32.tf32.f32 "
        "{%0,%1,%2,%3}, {%4,%5,%6,%7}, {%8,%9}, {%0,%1,%2,%3};"
        : "+f"(d[0]), "+f"(d[1]), "+f"(d[2]), "+f"(d[3])
        : "r"(a[0]), "r"(a[1]), "r"(a[2]), "r"(a[3]), "r"(b0), "r"(b1));
}

// ============================================================
// Dummy kernel (ncu slot alignment: conv1 is the 4th launch).
// ============================================================
__global__ void k_nop1() {}

// ============================================================
// Kernel 0a: pre-split conv2 weights -> [chunk][kk=k*16+cc][o] hi/lo planes.
// ============================================================
__global__ void k_wsplit2(const float* __restrict__ w) {
    int idx = blockIdx.x * 256 + threadIdx.x;
    if (idx >= 8 * 80 * 64) return;
    int o = idx & 63;
    int kk = (idx >> 6) % 80;
    int chunk = idx / 5120;
    int k = kk >> 4, cc = kk & 15;
    float xv = w[o * 640 + (chunk * 16 + cc) * 5 + k];
    float hf, lf; split_tf32(xv, hf, lf);
    g_w2s[idx] = hf;
    g_w2s[8 * 80 * 64 + idx] = lf;
}

// ============================================================
// Kernel 0b: pre-split conv3 weights -> [chunk][kk=k*16+cc][o] hi/lo planes.
// ============================================================
__global__ void k_wsplit3(const float* __restrict__ w) {
    int idx = blockIdx.x * 256 + threadIdx.x;
    if (idx >= 4 * 48 * 64) return;
    int o = idx & 63;
    int kk = (idx >> 6) % 48;
    int chunk = idx / 3072;
    int k = kk >> 4, cc = kk & 15;
    float xv = w[o * 192 + (chunk * 16 + cc) * 3 + k];
    float hf, lf; split_tf32(xv, hf, lf);
    g_w3s[idx] = hf;
    g_w3s[4 * 48 * 64 + idx] = lf;
}

// ============================================================
// Kernel 1: conv1(k3) + BN + maxpool(3,2) + ReLU  -> g_h1   [profiled slot]
// ============================================================
__global__ void k_conv1(const float* __restrict__ x, const float* __restrict__ w,
                        const float* __restrict__ cb, const float* __restrict__ g,
                        const float* __restrict__ be, const float* __restrict__ m,
                        const float* __restrict__ v) {
    __shared__ float ws[O1 * 9];
    __shared__ float Ss[O1], Ts[O1];
    int b = blockIdx.y;
    int tid = threadIdx.x;
    for (int i = tid; i < O1 * 9; i += 128) ws[i] = w[i];
    if (tid < O1) {
        float s = g[tid] * rsqrtf(v[tid] + EPS_BN);
        Ss[tid] = s;
        Ts[tid] = (cb[tid] - m[tid]) * s + be[tid];
    }
    __syncthreads();
    int j = blockIdx.x * 128 + tid;
    if (j >= P1) return;

    const float* xb = x + (size_t)b * NCH * SIG_LEN;
    float xv[3][5];
#pragma unroll
    for (int c = 0; c < 3; c++)
#pragma unroll
        for (int k = 0; k < 5; k++)
            xv[c][k] = xb[c * SIG_LEN + 2 * j + k];

    float* h1 = g_h1 + (size_t)b * O1 * P1;
#pragma unroll 4
    for (int o = 0; o < O1; o++) {
        const float* wo = ws + o * 9;
        float y0 = 0.f, y1 = 0.f, y2 = 0.f;
#pragma unroll
        for (int c = 0; c < 3; c++) {
#pragma unroll
            for (int k = 0; k < 3; k++) {
                float wv = wo[c * 3 + k];
                y0 += xv[c][k] * wv;
                y1 += xv[c][k + 1] * wv;
                y2 += xv[c][k + 2] * wv;
            }
        }
        float S = Ss[o], T = Ts[o];
        float r = fmaxf(fmaxf(y0 * S + T, y1 * S + T), y2 * S + T);
        h1[(size_t)o * P1 + j] = fmaxf(r, 0.f);
    }
}

// ============================================================
// Kernel 2: conv2 via 3xTF32 mma.sync implicit GEMM (unchanged from R11).
// ============================================================
__global__ void k_conv2tc(const float* __restrict__ cb,
                          const float* __restrict__ g, const float* __restrict__ be,
                          const float* __restrict__ m, const float* __restrict__ v) {
    extern __shared__ float sm[];
    float* ws_hi = sm + OFF_WSHI;
    float* ws_lo = sm + OFF_WSLO;
    float* hs_hi = sm + OFF_HSHI;
    float* hs_lo = sm + OFF_HSLO;
    float* sdout = sm;
    __shared__ float Ss[O2], Ts[O2];

    int b = blockIdx.y;
    int bx = blockIdx.x;
    int tid = threadIdx.x;
    if (tid < O2) {
        float s = g[tid] * rsqrtf(v[tid] + EPS_BN);
        Ss[tid] = s;
        Ts[tid] = (cb[tid] - m[tid]) * s + be[tid];
    }
    int lane = tid & 31, wid = tid >> 5;
    int gid = lane >> 2, tig = lane & 3;
    int obase = (wid & 1) * 32;
    int nb0 = (wid >> 1) * 48;

    float acc[2][6][4];
#pragma unroll
    for (int f = 0; f < 2; f++)
#pragma unroll
        for (int i = 0; i < 6; i++)
#pragma unroll
            for (int jq = 0; jq < 4; jq++) acc[f][i][jq] = 0.f;

    const float* h1b = g_h1 + (size_t)b * O1 * P1;
    int gbase = bx * C2_NPB;

    for (int chunk = 0; chunk < 8; chunk++) {
        int c0 = chunk * 16;
        __syncthreads();
        for (int idx = tid; idx < 16 * 196; idx += 256) {
            int cc = idx / 196, p = idx - cc * 196;
            int gp = gbase + p;
            float xv = (gp < P1) ? h1b[(size_t)(c0 + cc) * P1 + gp] : 0.f;
            float hf, lf; split_tf32(xv, hf, lf);
            hs_hi[cc * HS_STR + p] = hf;
            hs_lo[cc * HS_STR + p] = lf;
        }
        {
            const float4* srch = (const float4*)(g_w2s + chunk * 5120);
            const float4* srcl = (const float4*)(g_w2s + 8 * 80 * 64 + chunk * 5120);
            for (int q = tid; q < 1280; q += 256) {
                int row = q >> 4, o4 = (q & 15) * 4;
                float4 hv = srch[q];
                float4 lv = srcl[q];
                *(float4*)&ws_hi[row * WS_STR + o4] = hv;
                *(float4*)&ws_lo[row * WS_STR + o4] = lv;
            }
        }
        __syncthreads();
#pragma unroll
        for (int s = 0; s < 10; s++) {
            int kkb = s * 8;
            int kq = s >> 1;
            int ccb = (s & 1) * 8;
            unsigned a_hi[2][4], a_lo[2][4];
            {
                int r0 = (kkb + tig) * WS_STR + obase + gid;
                int r1 = (kkb + tig + 4) * WS_STR + obase + gid;
#pragma unroll
                for (int f = 0; f < 2; f++) {
                    int off = f * 16;
                    a_hi[f][0] = __float_as_uint(ws_hi[r0 + off]);
                    a_hi[f][1] = __float_as_uint(ws_hi[r0 + off + 8]);
                    a_hi[f][2] = __float_as_uint(ws_hi[r1 + off]);
                    a_hi[f][3] = __float_as_uint(ws_hi[r1 + off + 8]);
                    a_lo[f][0] = __float_as_uint(ws_lo[r0 + off]);
                    a_lo[f][1] = __float_as_uint(ws_lo[r0 + off + 8]);
                    a_lo[f][2] = __float_as_uint(ws_lo[r1 + off]);
                    a_lo[f][3] = __float_as_uint(ws_lo[r1 + off + 8]);
                }
            }
            int hrow0 = (ccb + tig) * HS_STR;
            int hrow1 = (ccb + tig + 4) * HS_STR;
#pragma unroll
            for (int nf = 0; nf < 6; nf++) {
                int ncol = nb0 + nf * 8 + gid + kq;
                unsigned b_hi0 = __float_as_uint(hs_hi[hrow0 + ncol]);
                unsigned b_hi1 = __float_as_uint(hs_hi[hrow1 + ncol]);
                unsigned b_lo0 = __float_as_uint(hs_lo[hrow0 + ncol]);
                unsigned b_lo1 = __float_as_uint(hs_lo[hrow1 + ncol]);
#pragma unroll
                for (int f = 0; f < 2; f++) {
                    mma8(acc[f][nf], a_hi[f], b_hi0, b_hi1);
                    mma8(acc[f][nf], a_hi[f], b_lo0, b_lo1);
                    mma8(acc[f][nf], a_lo[f], b_hi0, b_hi1);
                }
            }
        }
    }
    __syncthreads();
#pragma unroll
    for (int f = 0; f < 2; f++) {
        int orow = obase + f * 16 + gid;
#pragma unroll
        for (int nf = 0; nf < 6; nf++) {
            int col = nb0 + nf * 8 + tig * 2;
            sdout[orow * SD_STR + col]     = acc[f][nf][0];
            sdout[orow * SD_STR + col + 1] = acc[f][nf][1];
            sdout[(orow + 8) * SD_STR + col]     = acc[f][nf][2];
            sdout[(orow + 8) * SD_STR + col + 1] = acc[f][nf][3];
        }
    }
    __syncthreads();
    float* h2b = g_h2 + (size_t)b * O2 * P2;
    for (int idx = tid; idx < 64 * C2_JPB; idx += 256) {
        int o = idx & 63, j = idx >> 6;
        int jg = bx * C2_JPB + j;
        if (jg < P2) {
            const float* r = sdout + o * SD_STR + 3 * j;
            float S = Ss[o], T = Ts[o];
            float a0 = r[0] * S + T;
            float a1 = r[1] * S + T;
            float a2 = r[2] * S + T;
            h2b[o * P2 + jg] = fmaxf(fmaxf(fmaxf(a0, a1), a2), 0.f);
        }
    }
}

// ============================================================
// Kernel 3: conv3 via 3xTF32 mma.sync implicit GEMM (clone of conv2 machinery).
// Block = (b, 95 pooled j, s2 overlapping pool) = 191 conv positions (+2 halo).
// M=64 (o), N=192, K=192 (4 chunks x 16ch x 3taps; kk = k*16+cc).
// 8 warps = 2 otiles (M32) x 4 nquads (N48); 6 K-steps/chunk.
// ============================================================
__global__ void k_conv3tc(const float* __restrict__ cb,
                          const float* __restrict__ g, const float* __restrict__ be,
                          const float* __restrict__ m, const float* __restrict__ v) {
    extern __shared__ float sm[];
    float* ws_hi = sm + OFF3_WSHI;   // [48][W3_STR]
    float* ws_lo = sm + OFF3_WSLO;
    float* hs_hi = sm + OFF3_HSHI;   // [16][H3_STR]
    float* hs_lo = sm + OFF3_HSLO;
    float* sdout = sm;               // [64][SD3_STR] aliased after mainloop
    __shared__ float Ss[O3], Ts[O3];

    int b = blockIdx.y;
    int bx = blockIdx.x;
    int tid = threadIdx.x;
    if (tid < O3) {
        float s = g[tid] * rsqrtf(v[tid] + EPS_BN);
        Ss[tid] = s;
        Ts[tid] = (cb[tid] - m[tid]) * s + be[tid];
    }
    int lane = tid & 31, wid = tid >> 5;
    int gid = lane >> 2, tig = lane & 3;
    int obase = (wid & 1) * 32;
    int nb0 = (wid >> 1) * 48;

    float acc[2][6][4];
#pragma unroll
    for (int f = 0; f < 2; f++)
#pragma unroll
        for (int i = 0; i < 6; i++)
#pragma unroll
            for (int jq = 0; jq < 4; jq++) acc[f][i][jq] = 0.f;

    const float* h2b = g_h2 + (size_t)b * O2 * P2;
    int p0 = bx * (2 * C3_JPB);      // conv position base (pool stride 2)

    for (int chunk = 0; chunk < 4; chunk++) {
        int c0 = chunk * 16;
        __syncthreads();
        // stage h2 tile (191 + 2 halo + slack), split hi/lo tf32
        for (int idx = tid; idx < 16 * 194; idx += 256) {
            int cc = idx / 194, p = idx - cc * 194;
            int gp = p0 + p;
            float xv = (gp < P2) ? h2b[(size_t)(c0 + cc) * P2 + gp] : 0.f;
            float hf, lf; split_tf32(xv, hf, lf);
            hs_hi[cc * H3_STR + p] = hf;
            hs_lo[cc * H3_STR + p] = lf;
        }
        // stage pre-split weights: raw float4 copies (48 kk x 64 o)
        {
            const float4* srch = (const float4*)(g_w3s + chunk * 3072);
            const float4* srcl = (const float4*)(g_w3s + 4 * 48 * 64 + chunk * 3072);
            for (int q = tid; q < 768; q += 256) {
                int row = q >> 4, o4 = (q & 15) * 4;
                float4 hv = srch[q];
                float4 lv = srcl[q];
                *(float4*)&ws_hi[row * W3_STR + o4] = hv;
                *(float4*)&ws_lo[row * W3_STR + o4] = lv;
            }
        }
        __syncthreads();
#pragma unroll
        for (int s = 0; s < 6; s++) {
            int kkb = s * 8;
            int kq = s >> 1;            // conv tap (0,0,1,1,2,2)
            int ccb = (s & 1) * 8;      // channel base within chunk
            unsigned a_hi[2][4], a_lo[2][4];
            {
                int r0 = (kkb + tig) * W3_STR + obase + gid;
                int r1 = (kkb + tig + 4) * W3_STR + obase + gid;
#pragma unroll
                for (int f = 0; f < 2; f++) {
                    int off = f * 16;
                    a_hi[f][0] = __float_as_uint(ws_hi[r0 + off]);
                    a_hi[f][1] = __float_as_uint(ws_hi[r0 + off + 8]);
                    a_hi[f][2] = __float_as_uint(ws_hi[r1 + off]);
                    a_hi[f][3] = __float_as_uint(ws_hi[r1 + off + 8]);
                    a_lo[f][0] = __float_as_uint(ws_lo[r0 + off]);
                    a_lo[f][1] = __float_as_uint(ws_lo[r0 + off + 8]);
                    a_lo[f][2] = __float_as_uint(ws_lo[r1 + off]);
                    a_lo[f][3] = __float_as_uint(ws_lo[r1 + off + 8]);
                }
            }
            int hrow0 = (ccb + tig) * H3_STR;
            int hrow1 = (ccb + tig + 4) * H3_STR;
#pragma unroll
            for (int nf = 0; nf < 6; nf++) {
                int ncol = nb0 + nf * 8 + gid + kq;
                unsigned b_hi0 = __float_as_uint(hs_hi[hrow0 + ncol]);
                unsigned b_hi1 = __float_as_uint(hs_hi[hrow1 + ncol]);
                unsigned b_lo0 = __float_as_uint(hs_lo[hrow0 + ncol]);
                unsigned b_lo1 = __float_as_uint(hs_lo[hrow1 + ncol]);
#pragma unroll
                for (int f = 0; f < 2; f++) {
                    mma8(acc[f][nf], a_hi[f], b_hi0, b_hi1);
                    mma8(acc[f][nf], a_hi[f], b_lo0, b_lo1);
                    mma8(acc[f][nf], a_lo[f], b_hi0, b_hi1);
                }
            }
        }
    }
    __syncthreads();
    // D fragments -> smem for cross-thread pooling
#pragma unroll
    for (int f = 0; f < 2; f++) {
        int orow = obase + f * 16 + gid;
#pragma unroll
        for (int nf = 0; nf < 6; nf++) {
            int col = nb0 + nf * 8 + tig * 2;
            sdout[orow * SD3_STR + col]     = acc[f][nf][0];
            sdout[orow * SD3_STR + col + 1] = acc[f][nf][1];
            sdout[(orow + 8) * SD3_STR + col]     = acc[f][nf][2];
            sdout[(orow + 8) * SD3_STR + col + 1] = acc[f][nf][3];
        }
    }
    __syncthreads();
    // maxpool(3,2) + BN + ReLU -> g_h3
    float* h3b = g_h3 + (size_t)b * O3 * P3;
    for (int idx = tid; idx < 64 * C3_JPB; idx += 256) {
        int o = idx % 64, j = idx / 64;
        int jg = bx * C3_JPB + j;
        if (jg < P3) {
            const float* r = sdout + o * SD3_STR + 2 * j;
            float S = Ss[o], T = Ts[o];
            float a0 = r[0] * S + T;
            float a1 = r[1] * S + T;
            float a2 = r[2] * S + T;
            h3b[o * P3 + jg] = fmaxf(fmaxf(fmaxf(a0, a1), a2), 0.f);
        }
    }
}

// ============================================================
// Kernel 4: fc1 split-K tiled GEMM: out[256,48] = h3 @ W^T, 28 K-splits.
// ============================================================
__global__ void k_fc1gemm(const float* __restrict__ w) {
    __shared__ float hsm[32][65];
    __shared__ float wsm[48][65];
    int bt = blockIdx.x * 32;
    int ks = blockIdx.y;
    int t = threadIdx.x;
    int tx = t & 15;
    int ty = t >> 4;
    float acc[2][3] = {};
    int kbase = ks * FC_KC;
#pragma unroll 1
    for (int kk = 0; kk < FC_KC; kk += 64) {
        __syncthreads();
        for (int idx = t; idx < 32 * 16; idx += 256) {
            int r = idx >> 4, c4 = (idx & 15) * 4;
            float4 vv = *(const float4*)(g_h3 + (size_t)(bt + r) * FC_IN + kbase + kk + c4);
            hsm[r][c4] = vv.x; hsm[r][c4 + 1] = vv.y; hsm[r][c4 + 2] = vv.z; hsm[r][c4 + 3] = vv.w;
        }
        for (int idx = t; idx < 48 * 16; idx += 256) {
            int r = idx >> 4, c4 = (idx & 15) * 4;
            float4 vv = *(const float4*)(w + (size_t)r * FC_IN + kbase + kk + c4);
            wsm[r][c4] = vv.x; wsm[r][c4 + 1] = vv.y; wsm[r][c4 + 2] = vv.z; wsm[r][c4 + 3] = vv.w;
        }
        __syncthreads();
#pragma unroll 8
        for (int k = 0; k < 64; k++) {
            float h0 = hsm[2 * ty][k], h1 = hsm[2 * ty + 1][k];
            float w0 = wsm[3 * tx][k], w1 = wsm[3 * tx + 1][k], w2 = wsm[3 * tx + 2][k];
            acc[0][0] += h0 * w0; acc[0][1] += h0 * w1; acc[0][2] += h0 * w2;
            acc[1][0] += h1 * w0; acc[1][1] += h1 * w1; acc[1][2] += h1 * w2;
        }
    }
#pragma unroll
    for (int i = 0; i < 2; i++)
#pragma unroll
        for (int j = 0; j < 3; j++)
            g_fc1p[ks][bt + 2 * ty + i][3 * tx + j] = acc[i][j];
}

// ============================================================
// Kernel 5: reduce fc1 partials (+bias,ReLU) -> fc2 -> fc3 -> fc4 -> tanh
//           -> A = theta @ basis^T. One block, thread = batch.
// ============================================================
__global__ void k_fchead(const float* __restrict__ b1,
                         const float* __restrict__ w2, const float* __restrict__ b2,
                         const float* __restrict__ w3, const float* __restrict__ b3,
                         const float* __restrict__ w4, const float* __restrict__ b4,
                         const float* __restrict__ basis) {
    __shared__ float s2[1536], sb2[32], s3[512], sb3[16], s4[80], sb4[5], sbas[60], sb1[48];
    int t = threadIdx.x;
    for (int i = t; i < 1536; i += 256) s2[i] = w2[i];
    for (int i = t; i < 512; i += 256) s3[i] = w3[i];
    if (t < 80) s4[t] = w4[t];
    if (t < 48) sb1[t] = b1[t];
    if (t < 32) sb2[t] = b2[t];
    if (t < 16) sb3[t] = b3[t];
    if (t < 5)  sb4[t] = b4[t];
    if (t < 60) sbas[t] = basis[t];
    __syncthreads();
    int b = t;
    float x1[48];
#pragma unroll
    for (int i = 0; i < 48; i++) {
        float s = sb1[i];
#pragma unroll
        for (int ks = 0; ks < FC_NS; ks++) s += g_fc1p[ks][b][i];
        x1[i] = fmaxf(s, 0.f);
    }
    float x2[32];
#pragma unroll
    for (int o = 0; o < 32; o++) {
        float s = sb2[o];
#pragma unroll
        for (int i = 0; i < 48; i++) s += x1[i] * s2[o * 48 + i];
        x2[o] = fmaxf(s, 0.f);
    }
    float x3[16];
#pragma unroll
    for (int o = 0; o < 16; o++) {
        float s = sb3[o];
#pragma unroll
        for (int i = 0; i < 32; i++) s += x2[i] * s3[o * 32 + i];
        x3[o] = fmaxf(s, 0.f);
    }
    float th[5];
#pragma unroll
    for (int o = 0; o < 5; o++) {
        float s = sb4[o];
#pragma unroll
        for (int i = 0; i < 16; i++) s += x3[i] * s4[o * 16 + i];
        th[o] = tanhf(s);
    }
#pragma unroll
    for (int r = 0; r < 12; r++) {
        float s = 0.f;
#pragma unroll
        for (int jq = 0; jq < 5; jq++) s += th[jq] * sbas[r * 5 + jq];
        g_A[b * 12 + r] = s;
    }
}

// ============================================================
// Kernel 6: exact CPAB integration of the grid + linear interpolation of x.
// ============================================================
__global__ void k_warp(const float* __restrict__ x, float* __restrict__ out) {
    __shared__ float a_s[6], b_s[6];
    int b = blockIdx.y;
    if (threadIdx.x < 12) {
        float val = g_A[b * 12 + threadIdx.x];
        if (threadIdx.x & 1) b_s[threadIdx.x >> 1] = val;
        else                 a_s[threadIdx.x >> 1] = val;
    }
    __syncthreads();
    int i = blockIdx.x * 256 + threadIdx.x;

    float xt = (float)i * (1.0f / 2047.0f);
    float t = 1.0f;
#pragma unroll 1
    for (int it = 0; it < 7; it++) {
        int c = (int)floorf(xt * 6.0f);
        c = max(0, min(c, 5));
        float a = a_s[c], bb = b_s[c];
        float vv = a * xt + bb;
        float xbn = (vv >= 0.f) ? (float)(c + 1) / 6.0f : (float)c / 6.0f;
        bool big = fabsf(a) > 1e-8f;
        float a_sv = big ? a : 1.0f;
        float z  = xt  + bb / a_sv;
        float zb = xbn + bb / a_sv;
        float zden = (fabsf(z) > 1e-12f) ? z : 1e-12f;
        float ratio = zb / zden;
        float t_exp = logf(fmaxf(ratio, 1e-12f)) / a_sv;
        float v_sv = (fabsf(vv) > 1e-12f) ? vv : 1.0f;
        float t_lin = (xbn - xt) / v_sv;
        float thit = big ? t_exp : t_lin;
        bool valid = (fabsf(vv) > 1e-12f) && (thit > 0.f) && ((big ? ratio : 1.0f) > 0.f);
        if (!valid) thit = INFINITY;
        float tau = fminf(t, thit);
        float xn = big ? (z * expf(a * tau) - (z - xt)) : (xt + bb * tau);
        bool hit = (thit <= t);
        float nudge = (vv >= 0.f) ? 1e-6f : -1e-6f;
        xt = hit ? (xbn + nudge) : xn;
        xt = fminf(fmaxf(xt, 0.f), 1.f);
        t = fmaxf(t - tau, 0.f);
    }
    float p = fminf(fmaxf(xt, 0.f), 1.f) * 2047.0f;
    int x0 = (int)floorf(p);
    x0 = max(0, min(x0, 2046));
    float wgt = p - (float)x0;
    const float* xb = x + (size_t)b * NCH * SIG_LEN;
    float* ob = out + (size_t)b * NCH * SIG_LEN;
#pragma unroll
    for (int cch = 0; cch < NCH; cch++) {
        float d0 = xb[cch * SIG_LEN + x0];
        float d1 = xb[cch * SIG_LEN + x0 + 1];
        ob[cch * SIG_LEN + i] = d0 * (1.0f - wgt) + d1 * wgt;
    }
}

// ============================================================
extern "C" void kernel_launch(void* const* d_in, const int* in_sizes, int n_in,
                              void* d_out, int out_size) {
    const float* x    = (const float*)d_in[0];
    const float* c1w  = (const float*)d_in[1];
    const float* c1b  = (const float*)d_in[2];
    const float* bn1g = (const float*)d_in[3];
    const float* bn1b = (const float*)d_in[4];
    const float* bn1m = (const float*)d_in[5];
    const float* bn1v = (const float*)d_in[6];
    const float* c2w  = (const float*)d_in[7];
    const float* c2b  = (const float*)d_in[8];
    const float* bn2g = (const float*)d_in[9];
    const float* bn2b = (const float*)d_in[10];
    const float* bn2m = (const float*)d_in[11];
    const float* bn2v = (const float*)d_in[12];
    const float* c3w  = (const float*)d_in[13];
    const float* c3b  = (const float*)d_in[14];
    const float* bn3g = (const float*)d_in[15];
    const float* bn3b = (const float*)d_in[16];
    const float* bn3m = (const float*)d_in[17];
    const float* bn3v = (const float*)d_in[18];
    const float* fc1w = (const float*)d_in[19];
    const float* fc1b = (const float*)d_in[20];
    const float* fc2w = (const float*)d_in[21];
    const float* fc2b = (const float*)d_in[22];
    const float* fc3w = (const float*)d_in[23];
    const float* fc3b = (const float*)d_in[24];
    const float* fc4w = (const float*)d_in[25];
    const float* fc4b = (const float*)d_in[26];
    const float* basis = (const float*)d_in[27];
    float* out = (float*)d_out;

    const int smem2 = SMEM_FLOATS * (int)sizeof(float);    // ~71.7 KB
    const int smem3 = SMEM3_FLOATS * (int)sizeof(float);   // ~53.2 KB
    cudaFuncSetAttribute(k_conv2tc, cudaFuncAttributeMaxDynamicSharedMemorySize, smem2);
    cudaFuncSetAttribute(k_conv3tc, cudaFuncAttributeMaxDynamicSharedMemorySize, smem3);

    // Slots 1-3: wsplit2, wsplit3, nop. Slot 4 (ncu-profiled): conv1.
    k_wsplit2<<<(8 * 80 * 64 + 255) / 256, 256>>>(c2w);
    k_wsplit3<<<(4 * 48 * 64 + 255) / 256, 256>>>(c3w);
    k_nop1<<<1, 32>>>();
    k_conv1<<<dim3((P1 + 127) / 128, BATCH), 128>>>(x, c1w, c1b, bn1g, bn1b, bn1m, bn1v);
    k_conv2tc<<<dim3(C2_NBX, BATCH), 256, smem2>>>(c2b, bn2g, bn2b, bn2m, bn2v);
    k_conv3tc<<<dim3(C3_NBX, BATCH), 256, smem3>>>(c3b, bn3g, bn3b, bn3m, bn3v);
    k_fc1gemm<<<dim3(8, FC_NS), 256>>>(fc1w);
    k_fchead<<<1, 256>>>(fc1b, fc2w, fc2b, fc3w, fc3b, fc4w, fc4b, basis);
    k_warp<<<dim3(SIG_LEN / 256, BATCH), 256>>>(x, out);
}

// round 13
// speedup vs baseline: 2.0547x; 1.2789x over previous
#include <cuda_runtime.h>
#include <cuda_bf16.h>
#include <cuda_fp16.h>
#include <math.h>

// ---------------- problem constants ----------------
#define BATCH 256
#define SIG_LEN 2048
#define NCH 3
#define O1 128
#define P1 1022          // conv1(k3) -> 2046, pool k3 s2 -> 1022
#define O2 64
#define P2 339           // conv2(k5) -> 1018, pool k3 s3 -> 339
#define O3 64
#define P3 168           // conv3(k3) -> 337, pool k3 s2 -> 168
#define FC_IN 10752      // 64*168
#define EPS_BN 1e-5f
#define FC_NS 28
#define FC_KC 384        // FC_IN / FC_NS

// conv2 fp16-MMA smem (u32 units). Block tile: M=64 (o), N=192 pre-pool pos.
#define W2S 72           // pair-row stride (64 + 8); 72%32==8 -> conflict-free
#define H2S 200          // 196 used; 200%32==8 -> conflict-free
#define OFF2_WH 0
#define OFF2_WL (40 * W2S)
#define OFF2_HH (2 * 40 * W2S)
#define OFF2_HL (2 * 40 * W2S + 8 * H2S)
#define SMEM2_U32 (2 * 40 * W2S + 2 * 8 * H2S)   // 8960 u32
#define SD_STR 193
#define SMEM2_BYTES (64 * SD_STR * 4)            // 49408 B (sdout dominates, aliased)
#define C2_NPB 192
#define C2_JPB 64
#define C2_NBX 6

// conv3 fp16-MMA smem. Block tile: M=64, N=192 conv pos (95 pooled, s2 pool).
#define W3S 72
#define H3S 200
#define OFF3_WH 0
#define OFF3_WL (24 * W3S)
#define OFF3_HH (2 * 24 * W3S)
#define OFF3_HL (2 * 24 * W3S + 8 * H3S)
#define SD3_STR 193
#define SMEM3_BYTES (64 * SD3_STR * 4)
#define C3_JPB 95
#define C3_NBX 2

// ---------------- device scratch (no allocations allowed) ----------------
__device__ float g_h1[(size_t)BATCH * O1 * P1];   // 134 MB
__device__ float g_h2[(size_t)BATCH * O2 * P2];   // 22 MB
__device__ float g_h3[(size_t)BATCH * O3 * P3];   // 11 MB
__device__ float g_fc1p[FC_NS][BATCH][48];
__device__ float g_A[BATCH * 12];
__device__ unsigned g_w2p[2 * 8 * 40 * 64];       // conv2 w: [hi/lo][chunk][kpair][o] fp16x2
__device__ unsigned g_w3p[2 * 4 * 24 * 64];       // conv3 w: [hi/lo][chunk][kpair][o] fp16x2

// ---------------- fp16 helpers ----------------
__device__ __forceinline__ void split_h(float x, __half& h, __half& l) {
    h = __float2half_rn(x);
    l = __float2half_rn(x - __half2float(h));
}
__device__ __forceinline__ unsigned pkh(__half a, __half b) {
    return (unsigned)__half_as_ushort(a) | ((unsigned)__half_as_ushort(b) << 16);
}
__device__ __forceinline__ void mma16(float* d, const unsigned* a, unsigned b0, unsigned b1) {
    asm volatile(
        "mma.sync.aligned.m16n8k16.row.col.f32.f16.f16.f32 "
        "{%0,%1,%2,%3}, {%4,%5,%6,%7}, {%8,%9}, {%0,%1,%2,%3};"
        : "+f"(d[0]), "+f"(d[1]), "+f"(d[2]), "+f"(d[3])
        : "r"(a[0]), "r"(a[1]), "r"(a[2]), "r"(a[3]), "r"(b0), "r"(b1));
}

// ============================================================
// Kernel 0a: conv2 weights -> packed fp16 hi/lo pair planes.
// kk = tap*16 + ch within chunk; pair pk packs (2pk, 2pk+1).
// ============================================================
__global__ void k_wsplit2(const float* __restrict__ w) {
    int idx = blockIdx.x * 256 + threadIdx.x;
    if (idx >= 8 * 40 * 64) return;
    int o = idx & 63;
    int pk = (idx >> 6) % 40;
    int chunk = idx / 2560;
    int kk0 = 2 * pk;
    int t = kk0 >> 4, c0 = kk0 & 15;
    float x0 = w[o * 640 + (chunk * 16 + c0) * 5 + t];
    float x1 = w[o * 640 + (chunk * 16 + c0 + 1) * 5 + t];
    __half h0, l0, h1, l1;
    split_h(x0, h0, l0);
    split_h(x1, h1, l1);
    g_w2p[idx] = pkh(h0, h1);
    g_w2p[8 * 40 * 64 + idx] = pkh(l0, l1);
}

// ============================================================
// Kernel 0b: conv3 weights -> packed fp16 hi/lo pair planes.
// ============================================================
__global__ void k_wsplit3(const float* __restrict__ w) {
    int idx = blockIdx.x * 256 + threadIdx.x;
    if (idx >= 4 * 24 * 64) return;
    int o = idx & 63;
    int pk = (idx >> 6) % 24;
    int chunk = idx / 1536;
    int kk0 = 2 * pk;
    int t = kk0 >> 4, c0 = kk0 & 15;
    float x0 = w[o * 192 + (chunk * 16 + c0) * 3 + t];
    float x1 = w[o * 192 + (chunk * 16 + c0 + 1) * 3 + t];
    __half h0, l0, h1, l1;
    split_h(x0, h0, l0);
    split_h(x1, h1, l1);
    g_w3p[idx] = pkh(h0, h1);
    g_w3p[4 * 24 * 64 + idx] = pkh(l0, l1);
}

// ============================================================
// Kernel 1: conv1(k3) + BN + maxpool(3,2) + ReLU  -> g_h1 (scalar; near fma ceiling)
// ============================================================
__global__ void k_conv1(const float* __restrict__ x, const float* __restrict__ w,
                        const float* __restrict__ cb, const float* __restrict__ g,
                        const float* __restrict__ be, const float* __restrict__ m,
                        const float* __restrict__ v) {
    __shared__ float ws[O1 * 9];
    __shared__ float Ss[O1], Ts[O1];
    int b = blockIdx.y;
    int tid = threadIdx.x;
    for (int i = tid; i < O1 * 9; i += 128) ws[i] = w[i];
    if (tid < O1) {
        float s = g[tid] * rsqrtf(v[tid] + EPS_BN);
        Ss[tid] = s;
        Ts[tid] = (cb[tid] - m[tid]) * s + be[tid];
    }
    __syncthreads();
    int j = blockIdx.x * 128 + tid;
    if (j >= P1) return;

    const float* xb = x + (size_t)b * NCH * SIG_LEN;
    float xv[3][5];
#pragma unroll
    for (int c = 0; c < 3; c++)
#pragma unroll
        for (int k = 0; k < 5; k++)
            xv[c][k] = xb[c * SIG_LEN + 2 * j + k];

    float* h1 = g_h1 + (size_t)b * O1 * P1;
#pragma unroll 4
    for (int o = 0; o < O1; o++) {
        const float* wo = ws + o * 9;
        float y0 = 0.f, y1 = 0.f, y2 = 0.f;
#pragma unroll
        for (int c = 0; c < 3; c++) {
#pragma unroll
            for (int k = 0; k < 3; k++) {
                float wv = wo[c * 3 + k];
                y0 += xv[c][k] * wv;
                y1 += xv[c][k + 1] * wv;
                y2 += xv[c][k + 2] * wv;
            }
        }
        float S = Ss[o], T = Ts[o];
        float r = fmaxf(fmaxf(y0 * S + T, y1 * S + T), y2 * S + T);
        h1[(size_t)o * P1 + j] = fmaxf(r, 0.f);
    }
}

// ============================================================
// Kernel 2: conv2 via fp16 2-limb m16n8k16 MMA (3 passes: hh, hl, lh).
// Block = (b, 64 pooled j) = 192 pre-pool positions. M=64, N=192.
// K = 8 chunks x 5 k16-steps (one tap each, 16 ch packed in pairs).
// 8 warps = 2 otiles (M32) x 4 nquads (N48).
// ============================================================
__global__ void k_conv2tc(const float* __restrict__ cb,
                          const float* __restrict__ g, const float* __restrict__ be,
                          const float* __restrict__ m, const float* __restrict__ v) {
    extern __shared__ unsigned smu[];
    unsigned* ws_h = smu + OFF2_WH;   // [40][W2S]
    unsigned* ws_l = smu + OFF2_WL;
    unsigned* hs_h = smu + OFF2_HH;   // [8][H2S]
    unsigned* hs_l = smu + OFF2_HL;
    float* sdout = (float*)smu;       // [64][SD_STR] aliased after mainloop
    __shared__ float Ss[O2], Ts[O2];

    int b = blockIdx.y;
    int bx = blockIdx.x;
    int tid = threadIdx.x;
    if (tid < O2) {
        float s = g[tid] * rsqrtf(v[tid] + EPS_BN);
        Ss[tid] = s;
        Ts[tid] = (cb[tid] - m[tid]) * s + be[tid];
    }
    int lane = tid & 31, wid = tid >> 5;
    int gid = lane >> 2, tig = lane & 3;
    int obase = (wid & 1) * 32;
    int nb0 = (wid >> 1) * 48;

    float acc[2][6][4];
#pragma unroll
    for (int f = 0; f < 2; f++)
#pragma unroll
        for (int i = 0; i < 6; i++)
#pragma unroll
            for (int jq = 0; jq < 4; jq++) acc[f][i][jq] = 0.f;

    const float* h1b = g_h1 + (size_t)b * O1 * P1;
    int gbase = bx * C2_NPB;

    for (int chunk = 0; chunk < 8; chunk++) {
        int c0 = chunk * 16;
        __syncthreads();
        // stage h1: 8 channel-pairs x 196 positions, split+pack fp16 at fill
        for (int idx = tid; idx < 8 * 196; idx += 256) {
            int cp = idx / 196, p = idx - cp * 196;
            int gp = gbase + p;
            float x0 = 0.f, x1 = 0.f;
            if (gp < P1) {
                x0 = h1b[(size_t)(c0 + 2 * cp) * P1 + gp];
                x1 = h1b[(size_t)(c0 + 2 * cp + 1) * P1 + gp];
            }
            __half h0, l0, h1v, l1;
            split_h(x0, h0, l0);
            split_h(x1, h1v, l1);
            hs_h[cp * H2S + p] = pkh(h0, h1v);
            hs_l[cp * H2S + p] = pkh(l0, l1);
        }
        // stage weights: raw uint4 copies of packed pair planes
        {
            const uint4* srch = (const uint4*)(g_w2p + chunk * 2560);
            const uint4* srcl = (const uint4*)(g_w2p + 8 * 40 * 64 + chunk * 2560);
            for (int q = tid; q < 640; q += 256) {
                int row = q >> 4, o4 = (q & 15) * 4;
                *(uint4*)&ws_h[row * W2S + o4] = srch[q];
                *(uint4*)&ws_l[row * W2S + o4] = srcl[q];
            }
        }
        __syncthreads();
#pragma unroll
        for (int s = 0; s < 5; s++) {          // k16 step == tap s
            unsigned ah[2][4], al[2][4];
            {
                int r0 = (8 * s + tig) * W2S + obase + gid;
                int r4 = (8 * s + tig + 4) * W2S + obase + gid;
#pragma unroll
                for (int f = 0; f < 2; f++) {
                    int off = f * 16;
                    ah[f][0] = ws_h[r0 + off];
                    ah[f][1] = ws_h[r0 + off + 8];
                    ah[f][2] = ws_h[r4 + off];
                    ah[f][3] = ws_h[r4 + off + 8];
                    al[f][0] = ws_l[r0 + off];
                    al[f][1] = ws_l[r0 + off + 8];
                    al[f][2] = ws_l[r4 + off];
                    al[f][3] = ws_l[r4 + off + 8];
                }
            }
            int hr0 = tig * H2S, hr4 = (tig + 4) * H2S;
#pragma unroll
            for (int nf = 0; nf < 6; nf++) {
                int ncol = nb0 + nf * 8 + gid + s;
                unsigned bh0 = hs_h[hr0 + ncol];
                unsigned bh1 = hs_h[hr4 + ncol];
                unsigned bl0 = hs_l[hr0 + ncol];
                unsigned bl1 = hs_l[hr4 + ncol];
#pragma unroll
                for (int f = 0; f < 2; f++) {
                    mma16(acc[f][nf], ah[f], bh0, bh1);
                    mma16(acc[f][nf], ah[f], bl0, bl1);
                    mma16(acc[f][nf], al[f], bh0, bh1);
                }
            }
        }
    }
    __syncthreads();
    // D fragments -> smem (aliased) for cross-thread pooling
#pragma unroll
    for (int f = 0; f < 2; f++) {
        int orow = obase + f * 16 + gid;
#pragma unroll
        for (int nf = 0; nf < 6; nf++) {
            int col = nb0 + nf * 8 + tig * 2;
            sdout[orow * SD_STR + col]     = acc[f][nf][0];
            sdout[orow * SD_STR + col + 1] = acc[f][nf][1];
            sdout[(orow + 8) * SD_STR + col]     = acc[f][nf][2];
            sdout[(orow + 8) * SD_STR + col + 1] = acc[f][nf][3];
        }
    }
    __syncthreads();
    // maxpool(3,3) + BN + ReLU -> g_h2
    float* h2b = g_h2 + (size_t)b * O2 * P2;
    for (int idx = tid; idx < 64 * C2_JPB; idx += 256) {
        int o = idx & 63, j = idx >> 6;
        int jg = bx * C2_JPB + j;
        if (jg < P2) {
            const float* r = sdout + o * SD_STR + 3 * j;
            float S = Ss[o], T = Ts[o];
            float a0 = r[0] * S + T;
            float a1 = r[1] * S + T;
            float a2 = r[2] * S + T;
            h2b[o * P2 + jg] = fmaxf(fmaxf(fmaxf(a0, a1), a2), 0.f);
        }
    }
}

// ============================================================
// Kernel 3: conv3 via fp16 2-limb m16n8k16 MMA (clone; 4 chunks x 3 steps).
// Block = (b, 95 pooled j, s2 pool) = 191 conv positions (+halo).
// ============================================================
__global__ void k_conv3tc(const float* __restrict__ cb,
                          const float* __restrict__ g, const float* __restrict__ be,
                          const float* __restrict__ m, const float* __restrict__ v) {
    extern __shared__ unsigned smu[];
    unsigned* ws_h = smu + OFF3_WH;   // [24][W3S]
    unsigned* ws_l = smu + OFF3_WL;
    unsigned* hs_h = smu + OFF3_HH;   // [8][H3S]
    unsigned* hs_l = smu + OFF3_HL;
    float* sdout = (float*)smu;       // [64][SD3_STR]
    __shared__ float Ss[O3], Ts[O3];

    int b = blockIdx.y;
    int bx = blockIdx.x;
    int tid = threadIdx.x;
    if (tid < O3) {
        float s = g[tid] * rsqrtf(v[tid] + EPS_BN);
        Ss[tid] = s;
        Ts[tid] = (cb[tid] - m[tid]) * s + be[tid];
    }
    int lane = tid & 31, wid = tid >> 5;
    int gid = lane >> 2, tig = lane & 3;
    int obase = (wid & 1) * 32;
    int nb0 = (wid >> 1) * 48;

    float acc[2][6][4];
#pragma unroll
    for (int f = 0; f < 2; f++)
#pragma unroll
        for (int i = 0; i < 6; i++)
#pragma unroll
            for (int jq = 0; jq < 4; jq++) acc[f][i][jq] = 0.f;

    const float* h2b = g_h2 + (size_t)b * O2 * P2;
    int p0 = bx * (2 * C3_JPB);

    for (int chunk = 0; chunk < 4; chunk++) {
        int c0 = chunk * 16;
        __syncthreads();
        for (int idx = tid; idx < 8 * 194; idx += 256) {
            int cp = idx / 194, p = idx - cp * 194;
            int gp = p0 + p;
            float x0 = 0.f, x1 = 0.f;
            if (gp < P2) {
                x0 = h2b[(size_t)(c0 + 2 * cp) * P2 + gp];
                x1 = h2b[(size_t)(c0 + 2 * cp + 1) * P2 + gp];
            }
            __half h0, l0, h1v, l1;
            split_h(x0, h0, l0);
            split_h(x1, h1v, l1);
            hs_h[cp * H3S + p] = pkh(h0, h1v);
            hs_l[cp * H3S + p] = pkh(l0, l1);
        }
        {
            const uint4* srch = (const uint4*)(g_w3p + chunk * 1536);
            const uint4* srcl = (const uint4*)(g_w3p + 4 * 24 * 64 + chunk * 1536);
            for (int q = tid; q < 384; q += 256) {
                int row = q >> 4, o4 = (q & 15) * 4;
                *(uint4*)&ws_h[row * W3S + o4] = srch[q];
                *(uint4*)&ws_l[row * W3S + o4] = srcl[q];
            }
        }
        __syncthreads();
#pragma unroll
        for (int s = 0; s < 3; s++) {
            unsigned ah[2][4], al[2][4];
            {
                int r0 = (8 * s + tig) * W3S + obase + gid;
                int r4 = (8 * s + tig + 4) * W3S + obase + gid;
#pragma unroll
                for (int f = 0; f < 2; f++) {
                    int off = f * 16;
                    ah[f][0] = ws_h[r0 + off];
                    ah[f][1] = ws_h[r0 + off + 8];
                    ah[f][2] = ws_h[r4 + off];
                    ah[f][3] = ws_h[r4 + off + 8];
                    al[f][0] = ws_l[r0 + off];
                    al[f][1] = ws_l[r0 + off + 8];
                    al[f][2] = ws_l[r4 + off];
                    al[f][3] = ws_l[r4 + off + 8];
                }
            }
            int hr0 = tig * H3S, hr4 = (tig + 4) * H3S;
#pragma unroll
            for (int nf = 0; nf < 6; nf++) {
                int ncol = nb0 + nf * 8 + gid + s;
                unsigned bh0 = hs_h[hr0 + ncol];
                unsigned bh1 = hs_h[hr4 + ncol];
                unsigned bl0 = hs_l[hr0 + ncol];
                unsigned bl1 = hs_l[hr4 + ncol];
#pragma unroll
                for (int f = 0; f < 2; f++) {
                    mma16(acc[f][nf], ah[f], bh0, bh1);
                    mma16(acc[f][nf], ah[f], bl0, bl1);
                    mma16(acc[f][nf], al[f], bh0, bh1);
                }
            }
        }
    }
    __syncthreads();
#pragma unroll
    for (int f = 0; f < 2; f++) {
        int orow = obase + f * 16 + gid;
#pragma unroll
        for (int nf = 0; nf < 6; nf++) {
            int col = nb0 + nf * 8 + tig * 2;
            sdout[orow * SD3_STR + col]     = acc[f][nf][0];
            sdout[orow * SD3_STR + col + 1] = acc[f][nf][1];
            sdout[(orow + 8) * SD3_STR + col]     = acc[f][nf][2];
            sdout[(orow + 8) * SD3_STR + col + 1] = acc[f][nf][3];
        }
    }
    __syncthreads();
    float* h3b = g_h3 + (size_t)b * O3 * P3;
    for (int idx = tid; idx < 64 * C3_JPB; idx += 256) {
        int o = idx % 64, j = idx / 64;
        int jg = bx * C3_JPB + j;
        if (jg < P3) {
            const float* r = sdout + o * SD3_STR + 2 * j;
            float S = Ss[o], T = Ts[o];
            float a0 = r[0] * S + T;
            float a1 = r[1] * S + T;
            float a2 = r[2] * S + T;
            h3b[o * P3 + jg] = fmaxf(fmaxf(fmaxf(a0, a1), a2), 0.f);
        }
    }
}

// ============================================================
// Kernel 4: fc1 split-K tiled GEMM: out[256,48] = h3 @ W^T, 28 K-splits.
// ============================================================
__global__ void k_fc1gemm(const float* __restrict__ w) {
    __shared__ float hsm[32][65];
    __shared__ float wsm[48][65];
    int bt = blockIdx.x * 32;
    int ks = blockIdx.y;
    int t = threadIdx.x;
    int tx = t & 15;
    int ty = t >> 4;
    float acc[2][3] = {};
    int kbase = ks * FC_KC;
#pragma unroll 1
    for (int kk = 0; kk < FC_KC; kk += 64) {
        __syncthreads();
        for (int idx = t; idx < 32 * 16; idx += 256) {
            int r = idx >> 4, c4 = (idx & 15) * 4;
            float4 vv = *(const float4*)(g_h3 + (size_t)(bt + r) * FC_IN + kbase + kk + c4);
            hsm[r][c4] = vv.x; hsm[r][c4 + 1] = vv.y; hsm[r][c4 + 2] = vv.z; hsm[r][c4 + 3] = vv.w;
        }
        for (int idx = t; idx < 48 * 16; idx += 256) {
            int r = idx >> 4, c4 = (idx & 15) * 4;
            float4 vv = *(const float4*)(w + (size_t)r * FC_IN + kbase + kk + c4);
            wsm[r][c4] = vv.x; wsm[r][c4 + 1] = vv.y; wsm[r][c4 + 2] = vv.z; wsm[r][c4 + 3] = vv.w;
        }
        __syncthreads();
#pragma unroll 8
        for (int k = 0; k < 64; k++) {
            float h0 = hsm[2 * ty][k], h1 = hsm[2 * ty + 1][k];
            float w0 = wsm[3 * tx][k], w1 = wsm[3 * tx + 1][k], w2 = wsm[3 * tx + 2][k];
            acc[0][0] += h0 * w0; acc[0][1] += h0 * w1; acc[0][2] += h0 * w2;
            acc[1][0] += h1 * w0; acc[1][1] += h1 * w1; acc[1][2] += h1 * w2;
        }
    }
#pragma unroll
    for (int i = 0; i < 2; i++)
#pragma unroll
        for (int j = 0; j < 3; j++)
            g_fc1p[ks][bt + 2 * ty + i][3 * tx + j] = acc[i][j];
}

// ============================================================
// Kernel 5: reduce fc1 partials (+bias,ReLU) -> fc2 -> fc3 -> fc4 -> tanh
//           -> A = theta @ basis^T. One block, thread = batch.
// ============================================================
__global__ void k_fchead(const float* __restrict__ b1,
                         const float* __restrict__ w2, const float* __restrict__ b2,
                         const float* __restrict__ w3, const float* __restrict__ b3,
                         const float* __restrict__ w4, const float* __restrict__ b4,
                         const float* __restrict__ basis) {
    __shared__ float s2[1536], sb2[32], s3[512], sb3[16], s4[80], sb4[5], sbas[60], sb1[48];
    int t = threadIdx.x;
    for (int i = t; i < 1536; i += 256) s2[i] = w2[i];
    for (int i = t; i < 512; i += 256) s3[i] = w3[i];
    if (t < 80) s4[t] = w4[t];
    if (t < 48) sb1[t] = b1[t];
    if (t < 32) sb2[t] = b2[t];
    if (t < 16) sb3[t] = b3[t];
    if (t < 5)  sb4[t] = b4[t];
    if (t < 60) sbas[t] = basis[t];
    __syncthreads();
    int b = t;
    float x1[48];
#pragma unroll
    for (int i = 0; i < 48; i++) {
        float s = sb1[i];
#pragma unroll
        for (int ks = 0; ks < FC_NS; ks++) s += g_fc1p[ks][b][i];
        x1[i] = fmaxf(s, 0.f);
    }
    float x2[32];
#pragma unroll
    for (int o = 0; o < 32; o++) {
        float s = sb2[o];
#pragma unroll
        for (int i = 0; i < 48; i++) s += x1[i] * s2[o * 48 + i];
        x2[o] = fmaxf(s, 0.f);
    }
    float x3[16];
#pragma unroll
    for (int o = 0; o < 16; o++) {
        float s = sb3[o];
#pragma unroll
        for (int i = 0; i < 32; i++) s += x2[i] * s3[o * 32 + i];
        x3[o] = fmaxf(s, 0.f);
    }
    float th[5];
#pragma unroll
    for (int o = 0; o < 5; o++) {
        float s = sb4[o];
#pragma unroll
        for (int i = 0; i < 16; i++) s += x3[i] * s4[o * 16 + i];
        th[o] = tanhf(s);
    }
#pragma unroll
    for (int r = 0; r < 12; r++) {
        float s = 0.f;
#pragma unroll
        for (int jq = 0; jq < 5; jq++) s += th[jq] * sbas[r * 5 + jq];
        g_A[b * 12 + r] = s;
    }
}

// ============================================================
// Kernel 6: exact CPAB integration of the grid + linear interpolation of x.
// ============================================================
__global__ void k_warp(const float* __restrict__ x, float* __restrict__ out) {
    __shared__ float a_s[6], b_s[6];
    int b = blockIdx.y;
    if (threadIdx.x < 12) {
        float val = g_A[b * 12 + threadIdx.x];
        if (threadIdx.x & 1) b_s[threadIdx.x >> 1] = val;
        else                 a_s[threadIdx.x >> 1] = val;
    }
    __syncthreads();
    int i = blockIdx.x * 256 + threadIdx.x;

    float xt = (float)i * (1.0f / 2047.0f);
    float t = 1.0f;
#pragma unroll 1
    for (int it = 0; it < 7; it++) {
        int c = (int)floorf(xt * 6.0f);
        c = max(0, min(c, 5));
        float a = a_s[c], bb = b_s[c];
        float vv = a * xt + bb;
        float xbn = (vv >= 0.f) ? (float)(c + 1) / 6.0f : (float)c / 6.0f;
        bool big = fabsf(a) > 1e-8f;
        float a_sv = big ? a : 1.0f;
        float z  = xt  + bb / a_sv;
        float zb = xbn + bb / a_sv;
        float zden = (fabsf(z) > 1e-12f) ? z : 1e-12f;
        float ratio = zb / zden;
        float t_exp = logf(fmaxf(ratio, 1e-12f)) / a_sv;
        float v_sv = (fabsf(vv) > 1e-12f) ? vv : 1.0f;
        float t_lin = (xbn - xt) / v_sv;
        float thit = big ? t_exp : t_lin;
        bool valid = (fabsf(vv) > 1e-12f) && (thit > 0.f) && ((big ? ratio : 1.0f) > 0.f);
        if (!valid) thit = INFINITY;
        float tau = fminf(t, thit);
        float xn = big ? (z * expf(a * tau) - (z - xt)) : (xt + bb * tau);
        bool hit = (thit <= t);
        float nudge = (vv >= 0.f) ? 1e-6f : -1e-6f;
        xt = hit ? (xbn + nudge) : xn;
        xt = fminf(fmaxf(xt, 0.f), 1.f);
        t = fmaxf(t - tau, 0.f);
    }
    float p = fminf(fmaxf(xt, 0.f), 1.f) * 2047.0f;
    int x0 = (int)floorf(p);
    x0 = max(0, min(x0, 2046));
    float wgt = p - (float)x0;
    const float* xb = x + (size_t)b * NCH * SIG_LEN;
    float* ob = out + (size_t)b * NCH * SIG_LEN;
#pragma unroll
    for (int cch = 0; cch < NCH; cch++) {
        float d0 = xb[cch * SIG_LEN + x0];
        float d1 = xb[cch * SIG_LEN + x0 + 1];
        ob[cch * SIG_LEN + i] = d0 * (1.0f - wgt) + d1 * wgt;
    }
}

// ============================================================
extern "C" void kernel_launch(void* const* d_in, const int* in_sizes, int n_in,
                              void* d_out, int out_size) {
    const float* x    = (const float*)d_in[0];
    const float* c1w  = (const float*)d_in[1];
    const float* c1b  = (const float*)d_in[2];
    const float* bn1g = (const float*)d_in[3];
    const float* bn1b = (const float*)d_in[4];
    const float* bn1m = (const float*)d_in[5];
    const float* bn1v = (const float*)d_in[6];
    const float* c2w  = (const float*)d_in[7];
    const float* c2b  = (const float*)d_in[8];
    const float* bn2g = (const float*)d_in[9];
    const float* bn2b = (const float*)d_in[10];
    const float* bn2m = (const float*)d_in[11];
    const float* bn2v = (const float*)d_in[12];
    const float* c3w  = (const float*)d_in[13];
    const float* c3b  = (const float*)d_in[14];
    const float* bn3g = (const float*)d_in[15];
    const float* bn3b = (const float*)d_in[16];
    const float* bn3m = (const float*)d_in[17];
    const float* bn3v = (const float*)d_in[18];
    const float* fc1w = (const float*)d_in[19];
    const float* fc1b = (const float*)d_in[20];
    const float* fc2w = (const float*)d_in[21];
    const float* fc2b = (const float*)d_in[22];
    const float* fc3w = (const float*)d_in[23];
    const float* fc3b = (const float*)d_in[24];
    const float* fc4w = (const float*)d_in[25];
    const float* fc4b = (const float*)d_in[26];
    const float* basis = (const float*)d_in[27];
    float* out = (float*)d_out;

    cudaFuncSetAttribute(k_conv2tc, cudaFuncAttributeMaxDynamicSharedMemorySize, SMEM2_BYTES);
    cudaFuncSetAttribute(k_conv3tc, cudaFuncAttributeMaxDynamicSharedMemorySize, SMEM3_BYTES);

    // Slots 1-3: wsplit2, wsplit3, conv1. Slot 4 (ncu-profiled): conv2tc.
    k_wsplit2<<<(8 * 40 * 64 + 255) / 256, 256>>>(c2w);
    k_wsplit3<<<(4 * 24 * 64 + 255) / 256, 256>>>(c3w);
    k_conv1<<<dim3((P1 + 127) / 128, BATCH), 128>>>(x, c1w, c1b, bn1g, bn1b, bn1m, bn1v);
    k_conv2tc<<<dim3(C2_NBX, BATCH), 256, SMEM2_BYTES>>>(c2b, bn2g, bn2b, bn2m, bn2v);
    k_conv3tc<<<dim3(C3_NBX, BATCH), 256, SMEM3_BYTES>>>(c3b, bn3g, bn3b, bn3m, bn3v);
    k_fc1gemm<<<dim3(8, FC_NS), 256>>>(fc1w);
    k_fchead<<<1, 256>>>(fc1b, fc2w, fc2b, fc3w, fc3b, fc4w, fc4b, basis);
    k_warp<<<dim3(SIG_LEN / 256, BATCH), 256>>>(x, out);
}